// round 1
// baseline (speedup 1.0000x reference)
#include <cuda_runtime.h>
#include <math.h>

#define EMB   1024
#define SEQ   1024
#define BATCH 8
#define NH    16
#define HD    64
#define TOK   (BATCH*SEQ)   // 8192

// Scratch (static device globals are the sanctioned scratch mechanism)
__device__ float g_proj[(size_t)TOK * 3 * EMB];  // 96 MB: q|k|v concatenated per token
__device__ float g_ctx[(size_t)TOK * EMB];       // 32 MB: attention output (pre out_proj)

// ---------------------------------------------------------------------------
// C[m][n] = bias[n] + sum_k A[m][k] * Bw[n][k]   (torch Linear: x @ W^T + b)
// 128x128 tile, BK=16, 256 threads, 8x8 micro-tile per thread.
// mode 0: A = Aext (qkv), C = g_proj     (in_proj)
// mode 1: A = g_ctx,      C = Cext(out)  (out_proj)
// ---------------------------------------------------------------------------
__global__ __launch_bounds__(256) void gemm_nt_bias(
    const float* __restrict__ Aext,
    const float* __restrict__ Bw,
    const float* __restrict__ bias,
    float* __restrict__ Cext,
    int M, int N, int K, int mode)
{
    const float* A = (mode == 0) ? Aext : g_ctx;
    float*       C = (mode == 0) ? g_proj : Cext;

    __shared__ float As[16][128];   // transposed: As[k][m]
    __shared__ float Bs[16][128];   // transposed: Bs[k][n]

    int tid = threadIdx.x;
    int tx  = tid & 15, ty = tid >> 4;
    int bm  = blockIdx.y * 128, bn = blockIdx.x * 128;

    // loader mapping: row lr (and lr+64), k-quad lk
    int lr = tid >> 2;
    int lk = (tid & 3) << 2;

    const float* Ap = A  + (size_t)(bm + lr) * K + lk;
    const float* Bp = Bw + (size_t)(bn + lr) * K + lk;

    float acc[8][8];
    #pragma unroll
    for (int i = 0; i < 8; i++)
        #pragma unroll
        for (int j = 0; j < 8; j++) acc[i][j] = 0.f;

    for (int k0 = 0; k0 < K; k0 += 16) {
        float4 a0 = *(const float4*)(Ap);
        float4 a1 = *(const float4*)(Ap + (size_t)64 * K);
        float4 b0 = *(const float4*)(Bp);
        float4 b1 = *(const float4*)(Bp + (size_t)64 * K);
        As[lk+0][lr]    = a0.x; As[lk+1][lr]    = a0.y; As[lk+2][lr]    = a0.z; As[lk+3][lr]    = a0.w;
        As[lk+0][lr+64] = a1.x; As[lk+1][lr+64] = a1.y; As[lk+2][lr+64] = a1.z; As[lk+3][lr+64] = a1.w;
        Bs[lk+0][lr]    = b0.x; Bs[lk+1][lr]    = b0.y; Bs[lk+2][lr]    = b0.z; Bs[lk+3][lr]    = b0.w;
        Bs[lk+0][lr+64] = b1.x; Bs[lk+1][lr+64] = b1.y; Bs[lk+2][lr+64] = b1.z; Bs[lk+3][lr+64] = b1.w;
        __syncthreads();

        #pragma unroll
        for (int kk = 0; kk < 16; kk++) {
            float4 aA = *(const float4*)&As[kk][ty*4];
            float4 aB = *(const float4*)&As[kk][ty*4+64];
            float4 bA = *(const float4*)&Bs[kk][tx*4];
            float4 bB = *(const float4*)&Bs[kk][tx*4+64];
            float ar[8] = {aA.x,aA.y,aA.z,aA.w,aB.x,aB.y,aB.z,aB.w};
            float br[8] = {bA.x,bA.y,bA.z,bA.w,bB.x,bB.y,bB.z,bB.w};
            #pragma unroll
            for (int i = 0; i < 8; i++)
                #pragma unroll
                for (int j = 0; j < 8; j++)
                    acc[i][j] += ar[i]*br[j];
        }
        __syncthreads();
        Ap += 16; Bp += 16;
    }

    #pragma unroll
    for (int i = 0; i < 8; i++) {
        int row = bm + ((i < 4) ? (ty*4 + i) : (64 + ty*4 + (i-4)));
        #pragma unroll
        for (int jh = 0; jh < 2; jh++) {
            int col = bn + ((jh == 0) ? (tx*4) : (64 + tx*4));
            float4 bv = *(const float4*)(bias + col);
            float4 o;
            o.x = acc[i][jh*4+0] + bv.x;
            o.y = acc[i][jh*4+1] + bv.y;
            o.z = acc[i][jh*4+2] + bv.z;
            o.w = acc[i][jh*4+3] + bv.w;
            *(float4*)(C + (size_t)row * N + col) = o;
        }
    }
}

// ---------------------------------------------------------------------------
// Flash-style attention, fp32. One CTA = (batch b, head h, 64-query block).
// 16 key blocks of 64. Online softmax. Reads g_proj, writes g_ctx.
// ---------------------------------------------------------------------------
struct FlashSmem {
    float Qs[64][64];   // [d][r]  (transposed, pre-scaled by 1/8)
    float Ks[64][65];   // [c][d]  (padded: stride 65 -> conflict-light scalar loads)
    float Vs[64][64];   // [c][d]
    float Ps[64][65];   // [r][c]
};

__global__ __launch_bounds__(256) void flash_attn_kernel()
{
    extern __shared__ char smem_raw[];
    FlashSmem* sm = (FlashSmem*)smem_raw;

    int tid = threadIdx.x;
    int tx  = tid & 15, ty = tid >> 4;
    int h   = blockIdx.y, b = blockIdx.z;
    int q0  = blockIdx.x * 64;
    int r0  = ty * 4, c0 = tx * 4, d0 = tx * 4;

    const float* base = g_proj + (size_t)b * SEQ * (3*EMB) + h * HD;

    // Load Q block transposed, fold in 1/sqrt(64)
    for (int e = tid; e < 64*16; e += 256) {
        int r = e >> 4, d4 = (e & 15) << 2;
        float4 v = *(const float4*)(base + (size_t)(q0 + r) * (3*EMB) + d4);
        sm->Qs[d4+0][r] = v.x * 0.125f;
        sm->Qs[d4+1][r] = v.y * 0.125f;
        sm->Qs[d4+2][r] = v.z * 0.125f;
        sm->Qs[d4+3][r] = v.w * 0.125f;
    }

    float m_i[4], l_i[4], acc[4][4];
    #pragma unroll
    for (int i = 0; i < 4; i++) {
        m_i[i] = -1e30f; l_i[i] = 0.f;
        #pragma unroll
        for (int j = 0; j < 4; j++) acc[i][j] = 0.f;
    }

    for (int kb = 0; kb < 16; kb++) {
        __syncthreads();   // Q writes (first iter) / prior PV reads complete
        const float* kbase = base + EMB   + (size_t)(kb*64) * (3*EMB);
        const float* vbase = base + 2*EMB + (size_t)(kb*64) * (3*EMB);
        for (int e = tid; e < 64*16; e += 256) {
            int c = e >> 4, d4 = (e & 15) << 2;
            float4 kv = *(const float4*)(kbase + (size_t)c * (3*EMB) + d4);
            sm->Ks[c][d4+0] = kv.x; sm->Ks[c][d4+1] = kv.y;
            sm->Ks[c][d4+2] = kv.z; sm->Ks[c][d4+3] = kv.w;
            float4 vv = *(const float4*)(vbase + (size_t)c * (3*EMB) + d4);
            *(float4*)&sm->Vs[c][d4] = vv;
        }
        __syncthreads();

        // S tile: 4x4 per thread
        float sc[4][4];
        #pragma unroll
        for (int i = 0; i < 4; i++)
            #pragma unroll
            for (int j = 0; j < 4; j++) sc[i][j] = 0.f;

        #pragma unroll 8
        for (int d = 0; d < 64; d++) {
            float4 q = *(const float4*)&sm->Qs[d][r0];
            float qv[4] = {q.x, q.y, q.z, q.w};
            float kv[4] = {sm->Ks[c0+0][d], sm->Ks[c0+1][d],
                           sm->Ks[c0+2][d], sm->Ks[c0+3][d]};
            #pragma unroll
            for (int i = 0; i < 4; i++)
                #pragma unroll
                for (int j = 0; j < 4; j++)
                    sc[i][j] += qv[i]*kv[j];
        }

        // Online softmax over this tile (row groups = 16 lanes sharing ty)
        #pragma unroll
        for (int i = 0; i < 4; i++) {
            float rm = fmaxf(fmaxf(sc[i][0], sc[i][1]), fmaxf(sc[i][2], sc[i][3]));
            rm = fmaxf(rm, __shfl_xor_sync(0xffffffffu, rm, 1));
            rm = fmaxf(rm, __shfl_xor_sync(0xffffffffu, rm, 2));
            rm = fmaxf(rm, __shfl_xor_sync(0xffffffffu, rm, 4));
            rm = fmaxf(rm, __shfl_xor_sync(0xffffffffu, rm, 8));
            float mnew  = fmaxf(m_i[i], rm);
            float alpha = __expf(m_i[i] - mnew);
            float rs = 0.f;
            #pragma unroll
            for (int j = 0; j < 4; j++) {
                sc[i][j] = __expf(sc[i][j] - mnew);
                rs += sc[i][j];
            }
            rs += __shfl_xor_sync(0xffffffffu, rs, 1);
            rs += __shfl_xor_sync(0xffffffffu, rs, 2);
            rs += __shfl_xor_sync(0xffffffffu, rs, 4);
            rs += __shfl_xor_sync(0xffffffffu, rs, 8);
            l_i[i] = l_i[i]*alpha + rs;
            m_i[i] = mnew;
            #pragma unroll
            for (int j = 0; j < 4; j++) acc[i][j] *= alpha;
            sm->Ps[r0+i][c0+0] = sc[i][0];
            sm->Ps[r0+i][c0+1] = sc[i][1];
            sm->Ps[r0+i][c0+2] = sc[i][2];
            sm->Ps[r0+i][c0+3] = sc[i][3];
        }
        __syncthreads();

        // O += P @ V
        #pragma unroll 8
        for (int kk = 0; kk < 64; kk++) {
            float4 v = *(const float4*)&sm->Vs[kk][d0];
            float vv[4] = {v.x, v.y, v.z, v.w};
            float pv[4] = {sm->Ps[r0+0][kk], sm->Ps[r0+1][kk],
                           sm->Ps[r0+2][kk], sm->Ps[r0+3][kk]};
            #pragma unroll
            for (int i = 0; i < 4; i++)
                #pragma unroll
                for (int j = 0; j < 4; j++)
                    acc[i][j] += pv[i]*vv[j];
        }
    }

    #pragma unroll
    for (int i = 0; i < 4; i++) {
        float inv = 1.f / l_i[i];
        float4 o;
        o.x = acc[i][0]*inv; o.y = acc[i][1]*inv;
        o.z = acc[i][2]*inv; o.w = acc[i][3]*inv;
        *(float4*)(g_ctx + (size_t)(b*SEQ + q0 + r0 + i) * EMB + h*HD + d0) = o;
    }
}

// ---------------------------------------------------------------------------
extern "C" void kernel_launch(void* const* d_in, const int* in_sizes, int n_in,
                              void* d_out, int out_size)
{
    (void)in_sizes; (void)n_in; (void)out_size;
    const float* qkv   = (const float*)d_in[0];
    const float* w_in  = (const float*)d_in[1];
    const float* b_in  = (const float*)d_in[2];
    const float* w_out = (const float*)d_in[3];
    const float* b_out = (const float*)d_in[4];
    float* out = (float*)d_out;

    cudaFuncSetAttribute(flash_attn_kernel,
                         cudaFuncAttributeMaxDynamicSharedMemorySize,
                         (int)sizeof(FlashSmem));

    // in_proj: [8192,1024] x [3072,1024]^T + b -> g_proj
    dim3 g1(3*EMB/128, TOK/128);
    gemm_nt_bias<<<g1, 256>>>(qkv, w_in, b_in, nullptr, TOK, 3*EMB, EMB, 0);

    // attention: g_proj -> g_ctx
    dim3 g2(SEQ/64, NH, BATCH);
    flash_attn_kernel<<<g2, 256, sizeof(FlashSmem)>>>();

    // out_proj: g_ctx x [1024,1024]^T + b -> out
    dim3 g3(EMB/128, TOK/128);
    gemm_nt_bias<<<g3, 256>>>(nullptr, w_out, b_out, out, TOK, EMB, EMB, 1);
}

// round 2
// speedup vs baseline: 2.1037x; 2.1037x over previous
#include <cuda_runtime.h>
#include <math.h>

#define EMB   1024
#define SEQ   1024
#define BATCH 8
#define NH    16
#define HD    64
#define TOK   (BATCH*SEQ)   // 8192

// Scratch
__device__ float g_proj[(size_t)TOK * 3 * EMB];  // q|k|v per token
__device__ float g_ctx[(size_t)TOK * EMB];       // attention output

// ---------------------------------------------------------------------------
__device__ __forceinline__ unsigned f2tf(float x) {
    unsigned u; asm("cvt.rna.tf32.f32 %0, %1;" : "=r"(u) : "f"(x)); return u;
}

__device__ __forceinline__ void mma_tf32(float c[4], const unsigned a[4], const unsigned b[2]) {
    asm volatile(
        "mma.sync.aligned.m16n8k8.row.col.f32.tf32.tf32.f32 "
        "{%0,%1,%2,%3}, {%4,%5,%6,%7}, {%8,%9}, {%0,%1,%2,%3};"
        : "+f"(c[0]), "+f"(c[1]), "+f"(c[2]), "+f"(c[3])
        : "r"(a[0]), "r"(a[1]), "r"(a[2]), "r"(a[3]), "r"(b[0]), "r"(b[1]));
}

// ---------------------------------------------------------------------------
// C[m][n] = bias[n] + sum_k A[m][k] * W[n][k]    (x @ W^T + b), tf32 tensor core
// CTA tile 128x128, BK=32, 256 threads (8 warps, 4x2), warp tile 32x64.
// Double-buffered smem, values stored pre-converted to tf32.
// ---------------------------------------------------------------------------
#define BK 32
#define TS 36   // padded k-stride (floats): frag banks = (4*gid + t) % 32, conflict-free

__global__ __launch_bounds__(256, 2) void gemm_tf32(
    const float* __restrict__ Aext,
    const float* __restrict__ Bw,
    const float* __restrict__ bias,
    float* __restrict__ Cext,
    int N, int K, int mode)
{
    const float* A = (mode == 0) ? Aext : g_ctx;
    float*       C = (mode == 0) ? g_proj : Cext;

    extern __shared__ float sm[];
    float* Abuf0 = sm;
    float* Abuf1 = sm + 128 * TS;
    float* Bbuf0 = sm + 2 * 128 * TS;
    float* Bbuf1 = sm + 3 * 128 * TS;

    int tid  = threadIdx.x;
    int lane = tid & 31, w = tid >> 5;
    int g = lane >> 2, t = lane & 3;
    int wm = (w >> 1) * 32, wn = (w & 1) * 64;
    int bm = blockIdx.y * 128, bn = blockIdx.x * 128;

    int lr = tid >> 3;        // 0..31 (row within 32-row slab)
    int lc = (tid & 7) * 4;   // 0..28 (k within chunk)

    const float* Ap = A  + (size_t)(bm + lr) * K + lc;
    const float* Bp = Bw + (size_t)(bn + lr) * K + lc;

    float4 ra[4], rb[4];

    auto LDG = [&](int chunk) {
        const float* ap = Ap + chunk * BK;
        const float* bp = Bp + chunk * BK;
        #pragma unroll
        for (int i = 0; i < 4; i++) {
            ra[i] = *(const float4*)(ap + (size_t)(32 * i) * K);
            rb[i] = *(const float4*)(bp + (size_t)(32 * i) * K);
        }
    };
    auto STS = [&](float* as, float* bs) {
        #pragma unroll
        for (int i = 0; i < 4; i++) {
            int r = lr + 32 * i;
            float* ad = as + r * TS + lc;
            ad[0] = __uint_as_float(f2tf(ra[i].x));
            ad[1] = __uint_as_float(f2tf(ra[i].y));
            ad[2] = __uint_as_float(f2tf(ra[i].z));
            ad[3] = __uint_as_float(f2tf(ra[i].w));
            float* bd = bs + r * TS + lc;
            bd[0] = __uint_as_float(f2tf(rb[i].x));
            bd[1] = __uint_as_float(f2tf(rb[i].y));
            bd[2] = __uint_as_float(f2tf(rb[i].z));
            bd[3] = __uint_as_float(f2tf(rb[i].w));
        }
    };

    float acc[2][8][4];
    #pragma unroll
    for (int ma = 0; ma < 2; ma++)
        #pragma unroll
        for (int na = 0; na < 8; na++)
            #pragma unroll
            for (int j = 0; j < 4; j++) acc[ma][na][j] = 0.f;

    auto COMPUTE = [&](const float* as, const float* bs) {
        #pragma unroll
        for (int ks = 0; ks < 4; ks++) {
            int k0 = ks * 8;
            unsigned af[2][4];
            #pragma unroll
            for (int ma = 0; ma < 2; ma++) {
                int r = wm + ma * 16 + g;
                af[ma][0] = __float_as_uint(as[(r    ) * TS + k0 + t]);
                af[ma][1] = __float_as_uint(as[(r + 8) * TS + k0 + t]);
                af[ma][2] = __float_as_uint(as[(r    ) * TS + k0 + t + 4]);
                af[ma][3] = __float_as_uint(as[(r + 8) * TS + k0 + t + 4]);
            }
            unsigned bf[8][2];
            #pragma unroll
            for (int na = 0; na < 8; na++) {
                int n = wn + na * 8 + g;
                bf[na][0] = __float_as_uint(bs[n * TS + k0 + t]);
                bf[na][1] = __float_as_uint(bs[n * TS + k0 + t + 4]);
            }
            #pragma unroll
            for (int ma = 0; ma < 2; ma++)
                #pragma unroll
                for (int na = 0; na < 8; na++)
                    mma_tf32(acc[ma][na], af[ma], bf[na]);
        }
    };

    int nch = K / BK;
    LDG(0);
    STS(Abuf0, Bbuf0);
    LDG(1);
    __syncthreads();

    for (int i = 0; i < nch; i++) {
        int cur = i & 1;
        if (i + 1 < nch) {
            if (cur) STS(Abuf0, Bbuf0); else STS(Abuf1, Bbuf1);
        }
        if (i + 2 < nch) LDG(i + 2);
        if (cur) COMPUTE(Abuf1, Bbuf1); else COMPUTE(Abuf0, Bbuf0);
        __syncthreads();
    }

    // epilogue
    #pragma unroll
    for (int ma = 0; ma < 2; ma++) {
        int r0 = bm + wm + ma * 16 + g;
        #pragma unroll
        for (int na = 0; na < 8; na++) {
            int col = bn + wn + na * 8 + 2 * t;
            float2 bv = *(const float2*)(bias + col);
            float2 o0 = { acc[ma][na][0] + bv.x, acc[ma][na][1] + bv.y };
            *(float2*)(C + (size_t)r0 * N + col) = o0;
            float2 o1 = { acc[ma][na][2] + bv.x, acc[ma][na][3] + bv.y };
            *(float2*)(C + (size_t)(r0 + 8) * N + col) = o1;
        }
    }
}

// ---------------------------------------------------------------------------
// Flash attention, tf32 tensor core. CTA = (b, h, 64-query block), 128 threads
// (4 warps, each owns 16 q-rows). 16 kv-blocks of 64. Online softmax in regs.
// ---------------------------------------------------------------------------
#define AST 68  // padded stride: conflict-free fragment gathers

__global__ __launch_bounds__(128) void attn_tf32()
{
    extern __shared__ float sm[];
    float* Qs = sm;                 // [64][AST]  (pre-scaled, tf32)
    float* Ks = sm + 64 * AST;      // [key][d]
    float* Vs = sm + 2 * 64 * AST;  // [key][d]
    float* Ps = sm + 3 * 64 * AST;  // [row][key]

    int tid = threadIdx.x, lane = tid & 31, w = tid >> 5;
    int g = lane >> 2, t = lane & 3;
    int h = blockIdx.y, b = blockIdx.z, q0 = blockIdx.x * 64;

    const float* base = g_proj + (size_t)b * SEQ * (3 * EMB) + h * HD;

    // Load Q (scale by 1/8, convert to tf32)
    {
        int r = tid >> 1, cb = (tid & 1) * 32;
        const float* src = base + (size_t)(q0 + r) * (3 * EMB) + cb;
        float* dst = Qs + r * AST + cb;
        #pragma unroll
        for (int i = 0; i < 8; i++) {
            float4 v = *(const float4*)(src + i * 4);
            dst[i*4+0] = __uint_as_float(f2tf(v.x * 0.125f));
            dst[i*4+1] = __uint_as_float(f2tf(v.y * 0.125f));
            dst[i*4+2] = __uint_as_float(f2tf(v.z * 0.125f));
            dst[i*4+3] = __uint_as_float(f2tf(v.w * 0.125f));
        }
    }

    float m_i[2] = { -1e30f, -1e30f }, l_i[2] = { 0.f, 0.f };
    float o[8][4];
    #pragma unroll
    for (int na = 0; na < 8; na++)
        #pragma unroll
        for (int j = 0; j < 4; j++) o[na][j] = 0.f;

    int r0 = w * 16 + g;  // this thread's first q-row (local)

    for (int kb = 0; kb < 16; kb++) {
        __syncthreads();   // K/V free to overwrite (and Q ready on kb=0)
        {
            int r = tid >> 1, cb = (tid & 1) * 32;
            const float* ksrc = base + EMB     + (size_t)(kb * 64 + r) * (3 * EMB) + cb;
            const float* vsrc = base + 2 * EMB + (size_t)(kb * 64 + r) * (3 * EMB) + cb;
            float* kd = Ks + r * AST + cb;
            float* vd = Vs + r * AST + cb;
            #pragma unroll
            for (int i = 0; i < 8; i++) {
                float4 kv = *(const float4*)(ksrc + i * 4);
                kd[i*4+0] = __uint_as_float(f2tf(kv.x));
                kd[i*4+1] = __uint_as_float(f2tf(kv.y));
                kd[i*4+2] = __uint_as_float(f2tf(kv.z));
                kd[i*4+3] = __uint_as_float(f2tf(kv.w));
                float4 vv = *(const float4*)(vsrc + i * 4);
                vd[i*4+0] = __uint_as_float(f2tf(vv.x));
                vd[i*4+1] = __uint_as_float(f2tf(vv.y));
                vd[i*4+2] = __uint_as_float(f2tf(vv.z));
                vd[i*4+3] = __uint_as_float(f2tf(vv.w));
            }
        }
        __syncthreads();

        // S = Q K^T  (warp: m16 x n64, k=64)
        float sc[8][4];
        #pragma unroll
        for (int na = 0; na < 8; na++)
            #pragma unroll
            for (int j = 0; j < 4; j++) sc[na][j] = 0.f;

        #pragma unroll
        for (int ks = 0; ks < 8; ks++) {
            int k0 = ks * 8;
            unsigned af[4];
            af[0] = __float_as_uint(Qs[(r0    ) * AST + k0 + t]);
            af[1] = __float_as_uint(Qs[(r0 + 8) * AST + k0 + t]);
            af[2] = __float_as_uint(Qs[(r0    ) * AST + k0 + t + 4]);
            af[3] = __float_as_uint(Qs[(r0 + 8) * AST + k0 + t + 4]);
            #pragma unroll
            for (int na = 0; na < 8; na++) {
                unsigned bf[2];
                int n = na * 8 + g;
                bf[0] = __float_as_uint(Ks[n * AST + k0 + t]);
                bf[1] = __float_as_uint(Ks[n * AST + k0 + t + 4]);
                mma_tf32(sc[na], af, bf);
            }
        }

        // Online softmax: this thread owns rows r0 (regs .0/.1) and r0+8 (.2/.3)
        #pragma unroll
        for (int half = 0; half < 2; half++) {
            float rm = -1e30f;
            #pragma unroll
            for (int na = 0; na < 8; na++)
                rm = fmaxf(rm, fmaxf(sc[na][half*2], sc[na][half*2+1]));
            rm = fmaxf(rm, __shfl_xor_sync(0xffffffffu, rm, 1));
            rm = fmaxf(rm, __shfl_xor_sync(0xffffffffu, rm, 2));
            float mn = fmaxf(m_i[half], rm);
            float al = __expf(m_i[half] - mn);
            float rs = 0.f;
            int prow = w * 16 + half * 8 + g;
            #pragma unroll
            for (int na = 0; na < 8; na++) {
                float p0 = __expf(sc[na][half*2]   - mn);
                float p1 = __expf(sc[na][half*2+1] - mn);
                rs += p0 + p1;
                float2 pp;
                pp.x = __uint_as_float(f2tf(p0));
                pp.y = __uint_as_float(f2tf(p1));
                *(float2*)(Ps + prow * AST + na * 8 + 2 * t) = pp;
                o[na][half*2]   *= al;
                o[na][half*2+1] *= al;
            }
            rs += __shfl_xor_sync(0xffffffffu, rs, 1);
            rs += __shfl_xor_sync(0xffffffffu, rs, 2);
            l_i[half] = l_i[half] * al + rs;
            m_i[half] = mn;
        }
        __syncwarp();   // P visible within warp (warp-private rows)

        // O += P V   (warp: m16 x n64, k=64 keys)
        #pragma unroll
        for (int ks = 0; ks < 8; ks++) {
            int k0 = ks * 8;
            unsigned af[4];
            af[0] = __float_as_uint(Ps[(r0    ) * AST + k0 + t]);
            af[1] = __float_as_uint(Ps[(r0 + 8) * AST + k0 + t]);
            af[2] = __float_as_uint(Ps[(r0    ) * AST + k0 + t + 4]);
            af[3] = __float_as_uint(Ps[(r0 + 8) * AST + k0 + t + 4]);
            #pragma unroll
            for (int na = 0; na < 8; na++) {
                unsigned bf[2];
                bf[0] = __float_as_uint(Vs[(k0 + t    ) * AST + na * 8 + g]);
                bf[1] = __float_as_uint(Vs[(k0 + t + 4) * AST + na * 8 + g]);
                mma_tf32(o[na], af, bf);
            }
        }
    }

    // Epilogue: normalize & write g_ctx
    float inv0 = 1.f / l_i[0], inv1 = 1.f / l_i[1];
    int row_g = b * SEQ + q0 + r0;
    #pragma unroll
    for (int na = 0; na < 8; na++) {
        int col = h * HD + na * 8 + 2 * t;
        float2 o0 = { o[na][0] * inv0, o[na][1] * inv0 };
        *(float2*)(g_ctx + (size_t)row_g * EMB + col) = o0;
        float2 o1 = { o[na][2] * inv1, o[na][3] * inv1 };
        *(float2*)(g_ctx + (size_t)(row_g + 8) * EMB + col) = o1;
    }
}

// ---------------------------------------------------------------------------
extern "C" void kernel_launch(void* const* d_in, const int* in_sizes, int n_in,
                              void* d_out, int out_size)
{
    (void)in_sizes; (void)n_in; (void)out_size;
    const float* qkv   = (const float*)d_in[0];
    const float* w_in  = (const float*)d_in[1];
    const float* b_in  = (const float*)d_in[2];
    const float* w_out = (const float*)d_in[3];
    const float* b_out = (const float*)d_in[4];
    float* out = (float*)d_out;

    int gemm_smem = 4 * 128 * TS * sizeof(float);          // 73728
    int attn_smem = 4 * 64 * AST * sizeof(float);          // 69632
    cudaFuncSetAttribute(gemm_tf32, cudaFuncAttributeMaxDynamicSharedMemorySize, gemm_smem);
    cudaFuncSetAttribute(attn_tf32, cudaFuncAttributeMaxDynamicSharedMemorySize, attn_smem);

    dim3 g1(3 * EMB / 128, TOK / 128);
    gemm_tf32<<<g1, 256, gemm_smem>>>(qkv, w_in, b_in, nullptr, 3 * EMB, EMB, 0);

    dim3 g2(SEQ / 64, NH, BATCH);
    attn_tf32<<<g2, 128, attn_smem>>>();

    dim3 g3(EMB / 128, TOK / 128);
    gemm_tf32<<<g3, 256, gemm_smem>>>(nullptr, w_out, b_out, out, EMB, EMB, 1);
}

// round 6
// speedup vs baseline: 2.7734x; 1.3184x over previous
#include <cuda_runtime.h>
#include <math.h>
#include <stdint.h>

#define EMB   1024
#define SEQ   1024
#define BATCH 8
#define NH    16
#define HD    64
#define TOK   (BATCH*SEQ)   // 8192

// Scratch
__device__ float g_proj[(size_t)TOK * 3 * EMB];  // q|k|v per token
__device__ float g_ctx[(size_t)TOK * EMB];       // attention output

// ---------------------------------------------------------------------------
__device__ __forceinline__ unsigned f2tf(float x) {
    unsigned u; asm("cvt.rna.tf32.f32 %0, %1;" : "=r"(u) : "f"(x)); return u;
}
__device__ __forceinline__ float ex2(float x) {
    float y; asm("ex2.approx.ftz.f32 %0, %1;" : "=f"(y) : "f"(x)); return y;
}
__device__ __forceinline__ void mma_tf32(float c[4], const unsigned a[4], const unsigned b[2]) {
    asm volatile(
        "mma.sync.aligned.m16n8k8.row.col.f32.tf32.tf32.f32 "
        "{%0,%1,%2,%3}, {%4,%5,%6,%7}, {%8,%9}, {%0,%1,%2,%3};"
        : "+f"(c[0]), "+f"(c[1]), "+f"(c[2]), "+f"(c[3])
        : "r"(a[0]), "r"(a[1]), "r"(a[2]), "r"(a[3]), "r"(b[0]), "r"(b[1]));
}

// ---------------------------------------------------------------------------
// GEMM — byte-identical to the Round-2 passing version.
// C[m][n] = bias[n] + sum_k A[m][k] * W[n][k]    (x @ W^T + b), tf32 HMMA
// CTA 128x128, BK=32, 256 threads (8 warps 4x2), warp tile 32x64, dbl-buffered.
// ---------------------------------------------------------------------------
#define BK 32
#define TS 36

__global__ __launch_bounds__(256, 2) void gemm_tf32(
    const float* __restrict__ Aext,
    const float* __restrict__ Bw,
    const float* __restrict__ bias,
    float* __restrict__ Cext,
    int N, int K, int mode)
{
    const float* A = (mode == 0) ? Aext : g_ctx;
    float*       C = (mode == 0) ? g_proj : Cext;

    extern __shared__ float sm[];
    float* Abuf0 = sm;
    float* Abuf1 = sm + 128 * TS;
    float* Bbuf0 = sm + 2 * 128 * TS;
    float* Bbuf1 = sm + 3 * 128 * TS;

    int tid  = threadIdx.x;
    int lane = tid & 31, w = tid >> 5;
    int g = lane >> 2, t = lane & 3;
    int wm = (w >> 1) * 32, wn = (w & 1) * 64;
    int bm = blockIdx.y * 128, bn = blockIdx.x * 128;

    int lr = tid >> 3;        // 0..31
    int lc = (tid & 7) * 4;   // 0..28

    const float* Ap = A  + (size_t)(bm + lr) * K + lc;
    const float* Bp = Bw + (size_t)(bn + lr) * K + lc;

    float4 ra[4], rb[4];

    auto LDG = [&](int chunk) {
        const float* ap = Ap + chunk * BK;
        const float* bp = Bp + chunk * BK;
        #pragma unroll
        for (int i = 0; i < 4; i++) {
            ra[i] = *(const float4*)(ap + (size_t)(32 * i) * K);
            rb[i] = *(const float4*)(bp + (size_t)(32 * i) * K);
        }
    };
    auto STS = [&](float* as, float* bs) {
        #pragma unroll
        for (int i = 0; i < 4; i++) {
            int r = lr + 32 * i;
            float* ad = as + r * TS + lc;
            ad[0] = __uint_as_float(f2tf(ra[i].x));
            ad[1] = __uint_as_float(f2tf(ra[i].y));
            ad[2] = __uint_as_float(f2tf(ra[i].z));
            ad[3] = __uint_as_float(f2tf(ra[i].w));
            float* bd = bs + r * TS + lc;
            bd[0] = __uint_as_float(f2tf(rb[i].x));
            bd[1] = __uint_as_float(f2tf(rb[i].y));
            bd[2] = __uint_as_float(f2tf(rb[i].z));
            bd[3] = __uint_as_float(f2tf(rb[i].w));
        }
    };

    float acc[2][8][4];
    #pragma unroll
    for (int ma = 0; ma < 2; ma++)
        #pragma unroll
        for (int na = 0; na < 8; na++)
            #pragma unroll
            for (int j = 0; j < 4; j++) acc[ma][na][j] = 0.f;

    auto COMPUTE = [&](const float* as, const float* bs) {
        #pragma unroll
        for (int ks = 0; ks < 4; ks++) {
            int k0 = ks * 8;
            unsigned af[2][4];
            #pragma unroll
            for (int ma = 0; ma < 2; ma++) {
                int r = wm + ma * 16 + g;
                af[ma][0] = __float_as_uint(as[(r    ) * TS + k0 + t]);
                af[ma][1] = __float_as_uint(as[(r + 8) * TS + k0 + t]);
                af[ma][2] = __float_as_uint(as[(r    ) * TS + k0 + t + 4]);
                af[ma][3] = __float_as_uint(as[(r + 8) * TS + k0 + t + 4]);
            }
            unsigned bf[8][2];
            #pragma unroll
            for (int na = 0; na < 8; na++) {
                int n = wn + na * 8 + g;
                bf[na][0] = __float_as_uint(bs[n * TS + k0 + t]);
                bf[na][1] = __float_as_uint(bs[n * TS + k0 + t + 4]);
            }
            #pragma unroll
            for (int ma = 0; ma < 2; ma++)
                #pragma unroll
                for (int na = 0; na < 8; na++)
                    mma_tf32(acc[ma][na], af[ma], bf[na]);
        }
    };

    int nch = K / BK;
    LDG(0);
    STS(Abuf0, Bbuf0);
    LDG(1);
    __syncthreads();

    for (int i = 0; i < nch; i++) {
        int cur = i & 1;
        if (i + 1 < nch) {
            if (cur) STS(Abuf0, Bbuf0); else STS(Abuf1, Bbuf1);
        }
        if (i + 2 < nch) LDG(i + 2);
        if (cur) COMPUTE(Abuf1, Bbuf1); else COMPUTE(Abuf0, Bbuf0);
        __syncthreads();
    }

    #pragma unroll
    for (int ma = 0; ma < 2; ma++) {
        int r0 = bm + wm + ma * 16 + g;
        #pragma unroll
        for (int na = 0; na < 8; na++) {
            int col = bn + wn + na * 8 + 2 * t;
            float2 bv = *(const float2*)(bias + col);
            float2 o0 = { acc[ma][na][0] + bv.x, acc[ma][na][1] + bv.y };
            *(float2*)(C + (size_t)r0 * N + col) = o0;
            float2 o1 = { acc[ma][na][2] + bv.x, acc[ma][na][3] + bv.y };
            *(float2*)(C + (size_t)(r0 + 8) * N + col) = o1;
        }
    }
}

// ---------------------------------------------------------------------------
// Flash attention — Round-2 fragment/index logic verbatim; mechanical changes
// only: 128-query CTA with 256 threads (8 warps), exp2-domain softmax.
// ---------------------------------------------------------------------------
#define AST 68

__global__ __launch_bounds__(256) void attn_tf32()
{
    extern __shared__ float smn[];
    float* Qs = smn;                  // [128][AST]
    float* Ks = smn + 128 * AST;      // [64][AST]
    float* Vs = smn + 192 * AST;      // [64][AST]
    float* Ps = smn + 256 * AST;      // [128][AST]

    int tid = threadIdx.x, lane = tid & 31, w = tid >> 5;
    int g = lane >> 2, t = lane & 3;
    int h = blockIdx.y, b = blockIdx.z, q0 = blockIdx.x * 128;

    const float* base = g_proj + (size_t)b * SEQ * (3 * EMB) + h * HD;
    const float SCL = 0.125f * 1.4426950408889634f;   // 1/sqrt(64) * log2(e)

    // Stage Q (scale by SCL, convert to tf32) — R2 loader, 256 threads/128 rows
    {
        int r = tid >> 1, cb = (tid & 1) * 32;
        const float* src = base + (size_t)(q0 + r) * (3 * EMB) + cb;
        float* dst = Qs + r * AST + cb;
        #pragma unroll
        for (int i = 0; i < 8; i++) {
            float4 v = *(const float4*)(src + i * 4);
            dst[i*4+0] = __uint_as_float(f2tf(v.x * SCL));
            dst[i*4+1] = __uint_as_float(f2tf(v.y * SCL));
            dst[i*4+2] = __uint_as_float(f2tf(v.z * SCL));
            dst[i*4+3] = __uint_as_float(f2tf(v.w * SCL));
        }
    }

    float m_i[2] = { -1e30f, -1e30f }, l_i[2] = { 0.f, 0.f };
    float o[8][4];
    #pragma unroll
    for (int na = 0; na < 8; na++)
        #pragma unroll
        for (int j = 0; j < 4; j++) o[na][j] = 0.f;

    int r0 = w * 16 + g;

    for (int kb = 0; kb < 16; kb++) {
        __syncthreads();
        // Stage K and V (tf32) — 256 threads / 64 keys, 16 elems each
        {
            int r = tid >> 2, cb = (tid & 3) * 16;
            const float* ksrc = base + EMB     + (size_t)(kb * 64 + r) * (3 * EMB) + cb;
            const float* vsrc = base + 2 * EMB + (size_t)(kb * 64 + r) * (3 * EMB) + cb;
            float* kd = Ks + r * AST + cb;
            float* vd = Vs + r * AST + cb;
            #pragma unroll
            for (int i = 0; i < 4; i++) {
                float4 kv = *(const float4*)(ksrc + i * 4);
                kd[i*4+0] = __uint_as_float(f2tf(kv.x));
                kd[i*4+1] = __uint_as_float(f2tf(kv.y));
                kd[i*4+2] = __uint_as_float(f2tf(kv.z));
                kd[i*4+3] = __uint_as_float(f2tf(kv.w));
                float4 vv = *(const float4*)(vsrc + i * 4);
                vd[i*4+0] = __uint_as_float(f2tf(vv.x));
                vd[i*4+1] = __uint_as_float(f2tf(vv.y));
                vd[i*4+2] = __uint_as_float(f2tf(vv.z));
                vd[i*4+3] = __uint_as_float(f2tf(vv.w));
            }
        }
        __syncthreads();

        // S = Q K^T (warp m16 x n64, k=64) — R2 verbatim
        float sc[8][4];
        #pragma unroll
        for (int na = 0; na < 8; na++)
            #pragma unroll
            for (int j = 0; j < 4; j++) sc[na][j] = 0.f;

        #pragma unroll
        for (int ks = 0; ks < 8; ks++) {
            int k0 = ks * 8;
            unsigned af[4];
            af[0] = __float_as_uint(Qs[(r0    ) * AST + k0 + t]);
            af[1] = __float_as_uint(Qs[(r0 + 8) * AST + k0 + t]);
            af[2] = __float_as_uint(Qs[(r0    ) * AST + k0 + t + 4]);
            af[3] = __float_as_uint(Qs[(r0 + 8) * AST + k0 + t + 4]);
            #pragma unroll
            for (int na = 0; na < 8; na++) {
                unsigned bf[2];
                int n = na * 8 + g;
                bf[0] = __float_as_uint(Ks[n * AST + k0 + t]);
                bf[1] = __float_as_uint(Ks[n * AST + k0 + t + 4]);
                mma_tf32(sc[na], af, bf);
            }
        }

        // Online softmax — R2 structure, exp2 domain (SCL pre-folded into Q)
        #pragma unroll
        for (int half = 0; half < 2; half++) {
            float rm = -1e30f;
            #pragma unroll
            for (int na = 0; na < 8; na++)
                rm = fmaxf(rm, fmaxf(sc[na][half*2], sc[na][half*2+1]));
            rm = fmaxf(rm, __shfl_xor_sync(0xffffffffu, rm, 1));
            rm = fmaxf(rm, __shfl_xor_sync(0xffffffffu, rm, 2));
            float mn = fmaxf(m_i[half], rm);
            float al = ex2(m_i[half] - mn);
            float rs = 0.f;
            int prow = w * 16 + half * 8 + g;
            #pragma unroll
            for (int na = 0; na < 8; na++) {
                float p0 = ex2(sc[na][half*2]   - mn);
                float p1 = ex2(sc[na][half*2+1] - mn);
                rs += p0 + p1;
                float2 pp;
                pp.x = __uint_as_float(f2tf(p0));
                pp.y = __uint_as_float(f2tf(p1));
                *(float2*)(Ps + prow * AST + na * 8 + 2 * t) = pp;
                o[na][half*2]   *= al;
                o[na][half*2+1] *= al;
            }
            rs += __shfl_xor_sync(0xffffffffu, rs, 1);
            rs += __shfl_xor_sync(0xffffffffu, rs, 2);
            l_i[half] = l_i[half] * al + rs;
            m_i[half] = mn;
        }
        __syncwarp();   // P rows are warp-private

        // O += P V — R2 verbatim
        #pragma unroll
        for (int ks = 0; ks < 8; ks++) {
            int k0 = ks * 8;
            unsigned af[4];
            af[0] = __float_as_uint(Ps[(r0    ) * AST + k0 + t]);
            af[1] = __float_as_uint(Ps[(r0 + 8) * AST + k0 + t]);
            af[2] = __float_as_uint(Ps[(r0    ) * AST + k0 + t + 4]);
            af[3] = __float_as_uint(Ps[(r0 + 8) * AST + k0 + t + 4]);
            #pragma unroll
            for (int na = 0; na < 8; na++) {
                unsigned bf[2];
                bf[0] = __float_as_uint(Vs[(k0 + t    ) * AST + na * 8 + g]);
                bf[1] = __float_as_uint(Vs[(k0 + t + 4) * AST + na * 8 + g]);
                mma_tf32(o[na], af, bf);
            }
        }
    }

    // Epilogue — R2 verbatim
    float inv0 = 1.f / l_i[0], inv1 = 1.f / l_i[1];
    int row_g = b * SEQ + q0 + r0;
    #pragma unroll
    for (int na = 0; na < 8; na++) {
        int col = h * HD + na * 8 + 2 * t;
        float2 o0 = { o[na][0] * inv0, o[na][1] * inv0 };
        *(float2*)(g_ctx + (size_t)row_g * EMB + col) = o0;
        float2 o1 = { o[na][2] * inv1, o[na][3] * inv1 };
        *(float2*)(g_ctx + (size_t)(row_g + 8) * EMB + col) = o1;
    }
}

// ---------------------------------------------------------------------------
extern "C" void kernel_launch(void* const* d_in, const int* in_sizes, int n_in,
                              void* d_out, int out_size)
{
    (void)in_sizes; (void)n_in; (void)out_size;
    const float* qkv   = (const float*)d_in[0];
    const float* w_in  = (const float*)d_in[1];
    const float* b_in  = (const float*)d_in[2];
    const float* w_out = (const float*)d_in[3];
    const float* b_out = (const float*)d_in[4];
    float* out = (float*)d_out;

    int gemm_smem = 4 * 128 * TS * sizeof(float);   // 73728
    int attn_smem = 384 * AST * sizeof(float);      // 104448
    cudaFuncSetAttribute(gemm_tf32, cudaFuncAttributeMaxDynamicSharedMemorySize, gemm_smem);
    cudaFuncSetAttribute(attn_tf32, cudaFuncAttributeMaxDynamicSharedMemorySize, attn_smem);

    dim3 g1(3 * EMB / 128, TOK / 128);
    gemm_tf32<<<g1, 256, gemm_smem>>>(qkv, w_in, b_in, nullptr, 3 * EMB, EMB, 0);

    dim3 g2(SEQ / 128, NH, BATCH);
    attn_tf32<<<g2, 256, attn_smem>>>();

    dim3 g3(EMB / 128, TOK / 128);
    gemm_tf32<<<g3, 256, gemm_smem>>>(nullptr, w_out, b_out, out, EMB, EMB, 1);
}

// round 7
// speedup vs baseline: 2.9561x; 1.0659x over previous
#include <cuda_runtime.h>
#include <math.h>
#include <stdint.h>

#define EMB   1024
#define SEQ   1024
#define BATCH 8
#define NH    16
#define HD    64
#define TOK   (BATCH*SEQ)   // 8192

// Scratch
__device__ float g_proj[(size_t)TOK * 3 * EMB];  // q|k|v per token
__device__ float g_ctx[(size_t)TOK * EMB];       // attention output

// ---------------------------------------------------------------------------
__device__ __forceinline__ unsigned f2tf(float x) {
    unsigned u; asm("cvt.rna.tf32.f32 %0, %1;" : "=r"(u) : "f"(x)); return u;
}
__device__ __forceinline__ float ex2(float x) {
    float y; asm("ex2.approx.ftz.f32 %0, %1;" : "=f"(y) : "f"(x)); return y;
}
__device__ __forceinline__ uint32_t s2u(const void* p) {
    return (uint32_t)__cvta_generic_to_shared(p);
}
__device__ __forceinline__ void mma_tf32(float c[4], const unsigned a[4], const unsigned b[2]) {
    asm volatile(
        "mma.sync.aligned.m16n8k8.row.col.f32.tf32.tf32.f32 "
        "{%0,%1,%2,%3}, {%4,%5,%6,%7}, {%8,%9}, {%0,%1,%2,%3};"
        : "+f"(c[0]), "+f"(c[1]), "+f"(c[2]), "+f"(c[3])
        : "r"(a[0]), "r"(a[1]), "r"(a[2]), "r"(a[3]), "r"(b[0]), "r"(b[1]));
}
// ldmatrix x4 on b32-reinterpreted 8x4-tf32 tiles (8 rows x 16B each).
__device__ __forceinline__ void ldsm_x4(unsigned r[4], uint32_t addr) {
    asm volatile("ldmatrix.sync.aligned.m8n8.x4.shared.b16 {%0,%1,%2,%3}, [%4];"
        : "=r"(r[0]), "=r"(r[1]), "=r"(r[2]), "=r"(r[3]) : "r"(addr));
}

// ---------------------------------------------------------------------------
// GEMM: C[m][n] = bias[n] + sum_k A[m][k] * W[n][k]   (x @ W^T + b), tf32 HMMA
// CTA 128x128, BK=32, 256 threads (8 warps 4x2), warp tile 32x64, dbl-buffered.
// Fragment loads via ldmatrix (layout in smem unchanged from R6).
// ---------------------------------------------------------------------------
#define BK 32
#define TS 36

__global__ __launch_bounds__(256, 2) void gemm_tf32(
    const float* __restrict__ Aext,
    const float* __restrict__ Bw,
    const float* __restrict__ bias,
    float* __restrict__ Cext,
    int N, int K, int mode)
{
    const float* A = (mode == 0) ? Aext : g_ctx;
    float*       C = (mode == 0) ? g_proj : Cext;

    extern __shared__ float sm[];
    float* Abuf0 = sm;
    float* Abuf1 = sm + 128 * TS;
    float* Bbuf0 = sm + 2 * 128 * TS;
    float* Bbuf1 = sm + 3 * 128 * TS;

    int tid  = threadIdx.x;
    int lane = tid & 31, w = tid >> 5;
    int g = lane >> 2, t = lane & 3;
    int wm = (w >> 1) * 32, wn = (w & 1) * 64;
    int bm = blockIdx.y * 128, bn = blockIdx.x * 128;

    int lr = tid >> 3;        // 0..31
    int lc = (tid & 7) * 4;   // 0..28

    const float* Ap = A  + (size_t)(bm + lr) * K + lc;
    const float* Bp = Bw + (size_t)(bn + lr) * K + lc;

    // ldmatrix per-lane source offsets (in floats, relative to buffer base):
    //   A frag (m16k8): row = wm + (lane&15), col = 4*(lane>>4)
    //   B frag (2x n8k8 pairs): row = wn + (lane&7) + 8*(lane>>4), col = 4*((lane>>3)&1)
    int a_off = (wm + (lane & 15)) * TS + 4 * (lane >> 4);
    int b_off = (wn + (lane & 7) + 8 * (lane >> 4)) * TS + 4 * ((lane >> 3) & 1);

    float4 ra[4], rb[4];

    auto LDG = [&](int chunk) {
        const float* ap = Ap + chunk * BK;
        const float* bp = Bp + chunk * BK;
        #pragma unroll
        for (int i = 0; i < 4; i++) {
            ra[i] = *(const float4*)(ap + (size_t)(32 * i) * K);
            rb[i] = *(const float4*)(bp + (size_t)(32 * i) * K);
        }
    };
    auto STS = [&](float* as, float* bs) {
        #pragma unroll
        for (int i = 0; i < 4; i++) {
            int r = lr + 32 * i;
            float* ad = as + r * TS + lc;
            ad[0] = __uint_as_float(f2tf(ra[i].x));
            ad[1] = __uint_as_float(f2tf(ra[i].y));
            ad[2] = __uint_as_float(f2tf(ra[i].z));
            ad[3] = __uint_as_float(f2tf(ra[i].w));
            float* bd = bs + r * TS + lc;
            bd[0] = __uint_as_float(f2tf(rb[i].x));
            bd[1] = __uint_as_float(f2tf(rb[i].y));
            bd[2] = __uint_as_float(f2tf(rb[i].z));
            bd[3] = __uint_as_float(f2tf(rb[i].w));
        }
    };

    float acc[2][8][4];
    #pragma unroll
    for (int ma = 0; ma < 2; ma++)
        #pragma unroll
        for (int na = 0; na < 8; na++)
            #pragma unroll
            for (int j = 0; j < 4; j++) acc[ma][na][j] = 0.f;

    auto COMPUTE = [&](const float* as, const float* bs) {
        uint32_t abase = s2u(as) + (a_off << 2);
        uint32_t bbase = s2u(bs) + (b_off << 2);
        #pragma unroll
        for (int ks = 0; ks < 4; ks++) {
            int k0 = ks * 8;
            unsigned af[2][4];
            ldsm_x4(af[0], abase + (k0 << 2));
            ldsm_x4(af[1], abase + ((16 * TS + k0) << 2));
            unsigned bf[4][4];   // j -> {bf(2j,0), bf(2j,1), bf(2j+1,0), bf(2j+1,1)}
            #pragma unroll
            for (int j = 0; j < 4; j++)
                ldsm_x4(bf[j], bbase + ((j * 16 * TS + k0) << 2));
            #pragma unroll
            for (int ma = 0; ma < 2; ma++)
                #pragma unroll
                for (int j = 0; j < 4; j++) {
                    unsigned b0[2] = { bf[j][0], bf[j][1] };
                    unsigned b1[2] = { bf[j][2], bf[j][3] };
                    mma_tf32(acc[ma][2 * j],     af[ma], b0);
                    mma_tf32(acc[ma][2 * j + 1], af[ma], b1);
                }
        }
    };

    int nch = K / BK;
    LDG(0);
    STS(Abuf0, Bbuf0);
    LDG(1);
    __syncthreads();

    for (int i = 0; i < nch; i++) {
        int cur = i & 1;
        if (i + 1 < nch) {
            if (cur) STS(Abuf0, Bbuf0); else STS(Abuf1, Bbuf1);
        }
        if (i + 2 < nch) LDG(i + 2);
        if (cur) COMPUTE(Abuf1, Bbuf1); else COMPUTE(Abuf0, Bbuf0);
        __syncthreads();
    }

    #pragma unroll
    for (int ma = 0; ma < 2; ma++) {
        int r0 = bm + wm + ma * 16 + g;
        #pragma unroll
        for (int na = 0; na < 8; na++) {
            int col = bn + wn + na * 8 + 2 * t;
            float2 bv = *(const float2*)(bias + col);
            float2 o0 = { acc[ma][na][0] + bv.x, acc[ma][na][1] + bv.y };
            *(float2*)(C + (size_t)r0 * N + col) = o0;
            float2 o1 = { acc[ma][na][2] + bv.x, acc[ma][na][3] + bv.y };
            *(float2*)(C + (size_t)(r0 + 8) * N + col) = o1;
        }
    }
}

// ---------------------------------------------------------------------------
// Flash attention — R6 logic; Q/K/P fragment loads via ldmatrix (same trick,
// smem layout unchanged). V-path fragments stay scalar (transposed access).
// ---------------------------------------------------------------------------
#define AST 68

__global__ __launch_bounds__(256) void attn_tf32()
{
    extern __shared__ float smn[];
    float* Qs = smn;                  // [128][AST]
    float* Ks = smn + 128 * AST;      // [64][AST]
    float* Vs = smn + 192 * AST;      // [64][AST]
    float* Ps = smn + 256 * AST;      // [128][AST]

    int tid = threadIdx.x, lane = tid & 31, w = tid >> 5;
    int g = lane >> 2, t = lane & 3;
    int h = blockIdx.y, b = blockIdx.z, q0 = blockIdx.x * 128;

    const float* base = g_proj + (size_t)b * SEQ * (3 * EMB) + h * HD;
    const float SCL = 0.125f * 1.4426950408889634f;   // 1/sqrt(64) * log2(e)

    // ldmatrix per-lane offsets (floats):
    int am_off = (w * 16 + (lane & 15)) * AST + 4 * (lane >> 4);            // A-style (Q/P)
    int bm_off = ((lane & 7) + 8 * (lane >> 4)) * AST + 4 * ((lane >> 3) & 1); // B-style (K)
    uint32_t qbase = s2u(Qs) + (am_off << 2);
    uint32_t pbase = s2u(Ps) + (am_off << 2);
    uint32_t kbase = s2u(Ks) + (bm_off << 2);

    // Stage Q (scale by SCL, convert to tf32)
    {
        int r = tid >> 1, cb = (tid & 1) * 32;
        const float* src = base + (size_t)(q0 + r) * (3 * EMB) + cb;
        float* dst = Qs + r * AST + cb;
        #pragma unroll
        for (int i = 0; i < 8; i++) {
            float4 v = *(const float4*)(src + i * 4);
            dst[i*4+0] = __uint_as_float(f2tf(v.x * SCL));
            dst[i*4+1] = __uint_as_float(f2tf(v.y * SCL));
            dst[i*4+2] = __uint_as_float(f2tf(v.z * SCL));
            dst[i*4+3] = __uint_as_float(f2tf(v.w * SCL));
        }
    }

    float m_i[2] = { -1e30f, -1e30f }, l_i[2] = { 0.f, 0.f };
    float o[8][4];
    #pragma unroll
    for (int na = 0; na < 8; na++)
        #pragma unroll
        for (int j = 0; j < 4; j++) o[na][j] = 0.f;

    int r0 = w * 16 + g;

    for (int kb = 0; kb < 16; kb++) {
        __syncthreads();
        // Stage K and V (tf32)
        {
            int r = tid >> 2, cb = (tid & 3) * 16;
            const float* ksrc = base + EMB     + (size_t)(kb * 64 + r) * (3 * EMB) + cb;
            const float* vsrc = base + 2 * EMB + (size_t)(kb * 64 + r) * (3 * EMB) + cb;
            float* kd = Ks + r * AST + cb;
            float* vd = Vs + r * AST + cb;
            #pragma unroll
            for (int i = 0; i < 4; i++) {
                float4 kv = *(const float4*)(ksrc + i * 4);
                kd[i*4+0] = __uint_as_float(f2tf(kv.x));
                kd[i*4+1] = __uint_as_float(f2tf(kv.y));
                kd[i*4+2] = __uint_as_float(f2tf(kv.z));
                kd[i*4+3] = __uint_as_float(f2tf(kv.w));
                float4 vv = *(const float4*)(vsrc + i * 4);
                vd[i*4+0] = __uint_as_float(f2tf(vv.x));
                vd[i*4+1] = __uint_as_float(f2tf(vv.y));
                vd[i*4+2] = __uint_as_float(f2tf(vv.z));
                vd[i*4+3] = __uint_as_float(f2tf(vv.w));
            }
        }
        __syncthreads();

        // S = Q K^T (warp m16 x n64, k=64)
        float sc[8][4];
        #pragma unroll
        for (int na = 0; na < 8; na++)
            #pragma unroll
            for (int j = 0; j < 4; j++) sc[na][j] = 0.f;

        #pragma unroll
        for (int ks = 0; ks < 8; ks++) {
            int k0 = ks * 8;
            unsigned af[4];
            ldsm_x4(af, qbase + (k0 << 2));
            unsigned bf[4][4];
            #pragma unroll
            for (int j = 0; j < 4; j++)
                ldsm_x4(bf[j], kbase + ((j * 16 * AST + k0) << 2));
            #pragma unroll
            for (int j = 0; j < 4; j++) {
                unsigned b0[2] = { bf[j][0], bf[j][1] };
                unsigned b1[2] = { bf[j][2], bf[j][3] };
                mma_tf32(sc[2 * j],     af, b0);
                mma_tf32(sc[2 * j + 1], af, b1);
            }
        }

        // Online softmax — exp2 domain
        #pragma unroll
        for (int half = 0; half < 2; half++) {
            float rm = -1e30f;
            #pragma unroll
            for (int na = 0; na < 8; na++)
                rm = fmaxf(rm, fmaxf(sc[na][half*2], sc[na][half*2+1]));
            rm = fmaxf(rm, __shfl_xor_sync(0xffffffffu, rm, 1));
            rm = fmaxf(rm, __shfl_xor_sync(0xffffffffu, rm, 2));
            float mn = fmaxf(m_i[half], rm);
            float al = ex2(m_i[half] - mn);
            float rs = 0.f;
            int prow = w * 16 + half * 8 + g;
            #pragma unroll
            for (int na = 0; na < 8; na++) {
                float p0 = ex2(sc[na][half*2]   - mn);
                float p1 = ex2(sc[na][half*2+1] - mn);
                rs += p0 + p1;
                float2 pp;
                pp.x = __uint_as_float(f2tf(p0));
                pp.y = __uint_as_float(f2tf(p1));
                *(float2*)(Ps + prow * AST + na * 8 + 2 * t) = pp;
                o[na][half*2]   *= al;
                o[na][half*2+1] *= al;
            }
            rs += __shfl_xor_sync(0xffffffffu, rs, 1);
            rs += __shfl_xor_sync(0xffffffffu, rs, 2);
            l_i[half] = l_i[half] * al + rs;
            m_i[half] = mn;
        }
        __syncwarp();   // P rows are warp-private

        // O += P V  (P frag via ldmatrix; V frags scalar as in R6)
        #pragma unroll
        for (int ks = 0; ks < 8; ks++) {
            int k0 = ks * 8;
            unsigned af[4];
            ldsm_x4(af, pbase + (k0 << 2));
            #pragma unroll
            for (int na = 0; na < 8; na++) {
                unsigned bf[2];
                bf[0] = __float_as_uint(Vs[(k0 + t    ) * AST + na * 8 + g]);
                bf[1] = __float_as_uint(Vs[(k0 + t + 4) * AST + na * 8 + g]);
                mma_tf32(o[na], af, bf);
            }
        }
    }

    // Epilogue
    float inv0 = 1.f / l_i[0], inv1 = 1.f / l_i[1];
    int row_g = b * SEQ + q0 + r0;
    #pragma unroll
    for (int na = 0; na < 8; na++) {
        int col = h * HD + na * 8 + 2 * t;
        float2 o0 = { o[na][0] * inv0, o[na][1] * inv0 };
        *(float2*)(g_ctx + (size_t)row_g * EMB + col) = o0;
        float2 o1 = { o[na][2] * inv1, o[na][3] * inv1 };
        *(float2*)(g_ctx + (size_t)(row_g + 8) * EMB + col) = o1;
    }
}

// ---------------------------------------------------------------------------
extern "C" void kernel_launch(void* const* d_in, const int* in_sizes, int n_in,
                              void* d_out, int out_size)
{
    (void)in_sizes; (void)n_in; (void)out_size;
    const float* qkv   = (const float*)d_in[0];
    const float* w_in  = (const float*)d_in[1];
    const float* b_in  = (const float*)d_in[2];
    const float* w_out = (const float*)d_in[3];
    const float* b_out = (const float*)d_in[4];
    float* out = (float*)d_out;

    int gemm_smem = 4 * 128 * TS * sizeof(float);   // 73728
    int attn_smem = 384 * AST * sizeof(float);      // 104448
    cudaFuncSetAttribute(gemm_tf32, cudaFuncAttributeMaxDynamicSharedMemorySize, gemm_smem);
    cudaFuncSetAttribute(attn_tf32, cudaFuncAttributeMaxDynamicSharedMemorySize, attn_smem);

    dim3 g1(3 * EMB / 128, TOK / 128);
    gemm_tf32<<<g1, 256, gemm_smem>>>(qkv, w_in, b_in, nullptr, 3 * EMB, EMB, 0);

    dim3 g2(SEQ / 128, NH, BATCH);
    attn_tf32<<<g2, 256, attn_smem>>>();

    dim3 g3(EMB / 128, TOK / 128);
    gemm_tf32<<<g3, 256, gemm_smem>>>(nullptr, w_out, b_out, out, EMB, EMB, 1);
}

// round 8
// speedup vs baseline: 3.5279x; 1.1934x over previous
#include <cuda_runtime.h>
#include <cuda_fp16.h>
#include <math.h>
#include <stdint.h>

#define EMB   1024
#define SEQ   1024
#define BATCH 8
#define NH    16
#define HD    64
#define TOK   (BATCH*SEQ)   // 8192

// Scratch
__device__ float g_proj[(size_t)TOK * 3 * EMB];  // q|k|v per token
__device__ float g_ctx[(size_t)TOK * EMB];       // attention output

// ---------------------------------------------------------------------------
__device__ __forceinline__ unsigned f2tf(float x) {
    unsigned u; asm("cvt.rna.tf32.f32 %0, %1;" : "=r"(u) : "f"(x)); return u;
}
__device__ __forceinline__ float ex2(float x) {
    float y; asm("ex2.approx.ftz.f32 %0, %1;" : "=f"(y) : "f"(x)); return y;
}
__device__ __forceinline__ uint32_t s2u(const void* p) {
    return (uint32_t)__cvta_generic_to_shared(p);
}
__device__ __forceinline__ void mma_tf32(float c[4], const unsigned a[4], const unsigned b[2]) {
    asm volatile(
        "mma.sync.aligned.m16n8k8.row.col.f32.tf32.tf32.f32 "
        "{%0,%1,%2,%3}, {%4,%5,%6,%7}, {%8,%9}, {%0,%1,%2,%3};"
        : "+f"(c[0]), "+f"(c[1]), "+f"(c[2]), "+f"(c[3])
        : "r"(a[0]), "r"(a[1]), "r"(a[2]), "r"(a[3]), "r"(b[0]), "r"(b[1]));
}
__device__ __forceinline__ void mma_f16(float c[4], const unsigned a[4],
                                        unsigned b0, unsigned b1) {
    asm volatile(
        "mma.sync.aligned.m16n8k16.row.col.f32.f16.f16.f32 "
        "{%0,%1,%2,%3}, {%4,%5,%6,%7}, {%8,%9}, {%0,%1,%2,%3};"
        : "+f"(c[0]), "+f"(c[1]), "+f"(c[2]), "+f"(c[3])
        : "r"(a[0]), "r"(a[1]), "r"(a[2]), "r"(a[3]), "r"(b0), "r"(b1));
}
__device__ __forceinline__ void ldsm_x4(unsigned r[4], uint32_t addr) {
    asm volatile("ldmatrix.sync.aligned.m8n8.x4.shared.b16 {%0,%1,%2,%3}, [%4];"
        : "=r"(r[0]), "=r"(r[1]), "=r"(r[2]), "=r"(r[3]) : "r"(addr));
}
__device__ __forceinline__ unsigned packh2(float a, float b) {
    __half2 h = __floats2half2_rn(a, b);
    return *(unsigned*)&h;
}

// ---------------------------------------------------------------------------
// GEMM: C[m][n] = bias[n] + sum_k A[m][k] * W[n][k]   (x @ W^T + b)
// fp16 operands, f32 accum, m16n8k16 HMMA. CTA 128x128, BK=32, 256 threads
// (8 warps 4x2), warp tile 32x64, double-buffered smem, ldmatrix fragments.
// ---------------------------------------------------------------------------
#define BK  32
#define TSH 40   // half-stride per row (80 bytes; rows 16B-aligned, LDSM conflict-free)

__global__ __launch_bounds__(256, 2) void gemm_f16(
    const float* __restrict__ Aext,
    const float* __restrict__ Bw,
    const float* __restrict__ bias,
    float* __restrict__ Cext,
    int N, int K, int mode)
{
    const float* A = (mode == 0) ? Aext : g_ctx;
    float*       C = (mode == 0) ? g_proj : Cext;

    extern __shared__ __half smh[];
    __half* Abuf0 = smh;
    __half* Abuf1 = smh + 128 * TSH;
    __half* Bbuf0 = smh + 2 * 128 * TSH;
    __half* Bbuf1 = smh + 3 * 128 * TSH;

    int tid  = threadIdx.x;
    int lane = tid & 31, w = tid >> 5;
    int g = lane >> 2, t = lane & 3;
    int wm = (w >> 1) * 32, wn = (w & 1) * 64;
    int bm = blockIdx.y * 128, bn = blockIdx.x * 128;

    int lr = tid >> 3;        // 0..31
    int lc = (tid & 7) * 4;   // 0..28

    const float* Ap = A  + (size_t)(bm + lr) * K + lc;
    const float* Bp = Bw + (size_t)(bn + lr) * K + lc;

    // ldmatrix per-lane byte offsets (relative to buffer base):
    //   A (m16k16 x4): row = wm + (lane&15), +16B for lanes 16-31 (k upper 8)
    //   B (n16k16 x4): row = wn + (lane&7) + 8*(lane>>4), +16B if (lane>>3)&1
    int a_off = (wm + (lane & 15)) * TSH * 2 + (lane >> 4) * 16;
    int b_off = (wn + (lane & 7) + 8 * (lane >> 4)) * TSH * 2 + ((lane >> 3) & 1) * 16;

    float4 ra[4], rb[4];

    auto LDG = [&](int chunk) {
        const float* ap = Ap + chunk * BK;
        const float* bp = Bp + chunk * BK;
        #pragma unroll
        for (int i = 0; i < 4; i++) {
            ra[i] = *(const float4*)(ap + (size_t)(32 * i) * K);
            rb[i] = *(const float4*)(bp + (size_t)(32 * i) * K);
        }
    };
    auto STS = [&](__half* as, __half* bs) {
        #pragma unroll
        for (int i = 0; i < 4; i++) {
            int r = lr + 32 * i;
            uint2 av = { packh2(ra[i].x, ra[i].y), packh2(ra[i].z, ra[i].w) };
            *(uint2*)(as + r * TSH + lc) = av;
            uint2 bv = { packh2(rb[i].x, rb[i].y), packh2(rb[i].z, rb[i].w) };
            *(uint2*)(bs + r * TSH + lc) = bv;
        }
    };

    float acc[2][8][4];
    #pragma unroll
    for (int ma = 0; ma < 2; ma++)
        #pragma unroll
        for (int na = 0; na < 8; na++)
            #pragma unroll
            for (int j = 0; j < 4; j++) acc[ma][na][j] = 0.f;

    auto COMPUTE = [&](const __half* as, const __half* bs) {
        uint32_t abase = s2u(as) + a_off;
        uint32_t bbase = s2u(bs) + b_off;
        #pragma unroll
        for (int s = 0; s < 2; s++) {           // two k16 steps per BK=32
            uint32_t ko = s * 32;               // 16 halves = 32 bytes
            unsigned af[2][4];
            ldsm_x4(af[0], abase + ko);
            ldsm_x4(af[1], abase + 16 * TSH * 2 + ko);
            #pragma unroll
            for (int j = 0; j < 4; j++) {       // n16 groups
                unsigned bf[4];
                ldsm_x4(bf, bbase + j * 16 * TSH * 2 + ko);
                #pragma unroll
                for (int ma = 0; ma < 2; ma++) {
                    mma_f16(acc[ma][2 * j],     af[ma], bf[0], bf[1]);
                    mma_f16(acc[ma][2 * j + 1], af[ma], bf[2], bf[3]);
                }
            }
        }
    };

    int nch = K / BK;
    LDG(0);
    STS(Abuf0, Bbuf0);
    LDG(1);
    __syncthreads();

    for (int i = 0; i < nch; i++) {
        int cur = i & 1;
        if (i + 1 < nch) {
            if (cur) STS(Abuf0, Bbuf0); else STS(Abuf1, Bbuf1);
        }
        if (i + 2 < nch) LDG(i + 2);
        if (cur) COMPUTE(Abuf1, Bbuf1); else COMPUTE(Abuf0, Bbuf0);
        __syncthreads();
    }

    #pragma unroll
    for (int ma = 0; ma < 2; ma++) {
        int r0 = bm + wm + ma * 16 + g;
        #pragma unroll
        for (int na = 0; na < 8; na++) {
            int col = bn + wn + na * 8 + 2 * t;
            float2 bv = *(const float2*)(bias + col);
            float2 o0 = { acc[ma][na][0] + bv.x, acc[ma][na][1] + bv.y };
            *(float2*)(C + (size_t)r0 * N + col) = o0;
            float2 o1 = { acc[ma][na][2] + bv.x, acc[ma][na][3] + bv.y };
            *(float2*)(C + (size_t)(r0 + 8) * N + col) = o1;
        }
    }
}

// ---------------------------------------------------------------------------
// Flash attention — unchanged from Round 7 (passing).
// ---------------------------------------------------------------------------
#define AST 68

__global__ __launch_bounds__(256) void attn_tf32()
{
    extern __shared__ float smn[];
    float* Qs = smn;                  // [128][AST]
    float* Ks = smn + 128 * AST;      // [64][AST]
    float* Vs = smn + 192 * AST;      // [64][AST]
    float* Ps = smn + 256 * AST;      // [128][AST]

    int tid = threadIdx.x, lane = tid & 31, w = tid >> 5;
    int g = lane >> 2, t = lane & 3;
    int h = blockIdx.y, b = blockIdx.z, q0 = blockIdx.x * 128;

    const float* base = g_proj + (size_t)b * SEQ * (3 * EMB) + h * HD;
    const float SCL = 0.125f * 1.4426950408889634f;   // 1/sqrt(64) * log2(e)

    int am_off = (w * 16 + (lane & 15)) * AST + 4 * (lane >> 4);
    int bm_off = ((lane & 7) + 8 * (lane >> 4)) * AST + 4 * ((lane >> 3) & 1);
    uint32_t qbase = s2u(Qs) + (am_off << 2);
    uint32_t pbase = s2u(Ps) + (am_off << 2);
    uint32_t kbase = s2u(Ks) + (bm_off << 2);

    {
        int r = tid >> 1, cb = (tid & 1) * 32;
        const float* src = base + (size_t)(q0 + r) * (3 * EMB) + cb;
        float* dst = Qs + r * AST + cb;
        #pragma unroll
        for (int i = 0; i < 8; i++) {
            float4 v = *(const float4*)(src + i * 4);
            dst[i*4+0] = __uint_as_float(f2tf(v.x * SCL));
            dst[i*4+1] = __uint_as_float(f2tf(v.y * SCL));
            dst[i*4+2] = __uint_as_float(f2tf(v.z * SCL));
            dst[i*4+3] = __uint_as_float(f2tf(v.w * SCL));
        }
    }

    float m_i[2] = { -1e30f, -1e30f }, l_i[2] = { 0.f, 0.f };
    float o[8][4];
    #pragma unroll
    for (int na = 0; na < 8; na++)
        #pragma unroll
        for (int j = 0; j < 4; j++) o[na][j] = 0.f;

    int r0 = w * 16 + g;

    for (int kb = 0; kb < 16; kb++) {
        __syncthreads();
        {
            int r = tid >> 2, cb = (tid & 3) * 16;
            const float* ksrc = base + EMB     + (size_t)(kb * 64 + r) * (3 * EMB) + cb;
            const float* vsrc = base + 2 * EMB + (size_t)(kb * 64 + r) * (3 * EMB) + cb;
            float* kd = Ks + r * AST + cb;
            float* vd = Vs + r * AST + cb;
            #pragma unroll
            for (int i = 0; i < 4; i++) {
                float4 kv = *(const float4*)(ksrc + i * 4);
                kd[i*4+0] = __uint_as_float(f2tf(kv.x));
                kd[i*4+1] = __uint_as_float(f2tf(kv.y));
                kd[i*4+2] = __uint_as_float(f2tf(kv.z));
                kd[i*4+3] = __uint_as_float(f2tf(kv.w));
                float4 vv = *(const float4*)(vsrc + i * 4);
                vd[i*4+0] = __uint_as_float(f2tf(vv.x));
                vd[i*4+1] = __uint_as_float(f2tf(vv.y));
                vd[i*4+2] = __uint_as_float(f2tf(vv.z));
                vd[i*4+3] = __uint_as_float(f2tf(vv.w));
            }
        }
        __syncthreads();

        float sc[8][4];
        #pragma unroll
        for (int na = 0; na < 8; na++)
            #pragma unroll
            for (int j = 0; j < 4; j++) sc[na][j] = 0.f;

        #pragma unroll
        for (int ks = 0; ks < 8; ks++) {
            int k0 = ks * 8;
            unsigned af[4];
            ldsm_x4(af, qbase + (k0 << 2));
            unsigned bf[4][4];
            #pragma unroll
            for (int j = 0; j < 4; j++)
                ldsm_x4(bf[j], kbase + ((j * 16 * AST + k0) << 2));
            #pragma unroll
            for (int j = 0; j < 4; j++) {
                unsigned b0[2] = { bf[j][0], bf[j][1] };
                unsigned b1[2] = { bf[j][2], bf[j][3] };
                mma_tf32(sc[2 * j],     af, b0);
                mma_tf32(sc[2 * j + 1], af, b1);
            }
        }

        #pragma unroll
        for (int half = 0; half < 2; half++) {
            float rm = -1e30f;
            #pragma unroll
            for (int na = 0; na < 8; na++)
                rm = fmaxf(rm, fmaxf(sc[na][half*2], sc[na][half*2+1]));
            rm = fmaxf(rm, __shfl_xor_sync(0xffffffffu, rm, 1));
            rm = fmaxf(rm, __shfl_xor_sync(0xffffffffu, rm, 2));
            float mn = fmaxf(m_i[half], rm);
            float al = ex2(m_i[half] - mn);
            float rs = 0.f;
            int prow = w * 16 + half * 8 + g;
            #pragma unroll
            for (int na = 0; na < 8; na++) {
                float p0 = ex2(sc[na][half*2]   - mn);
                float p1 = ex2(sc[na][half*2+1] - mn);
                rs += p0 + p1;
                float2 pp;
                pp.x = __uint_as_float(f2tf(p0));
                pp.y = __uint_as_float(f2tf(p1));
                *(float2*)(Ps + prow * AST + na * 8 + 2 * t) = pp;
                o[na][half*2]   *= al;
                o[na][half*2+1] *= al;
            }
            rs += __shfl_xor_sync(0xffffffffu, rs, 1);
            rs += __shfl_xor_sync(0xffffffffu, rs, 2);
            l_i[half] = l_i[half] * al + rs;
            m_i[half] = mn;
        }
        __syncwarp();

        #pragma unroll
        for (int ks = 0; ks < 8; ks++) {
            int k0 = ks * 8;
            unsigned af[4];
            ldsm_x4(af, pbase + (k0 << 2));
            #pragma unroll
            for (int na = 0; na < 8; na++) {
                unsigned bf[2];
                bf[0] = __float_as_uint(Vs[(k0 + t    ) * AST + na * 8 + g]);
                bf[1] = __float_as_uint(Vs[(k0 + t + 4) * AST + na * 8 + g]);
                mma_tf32(o[na], af, bf);
            }
        }
    }

    float inv0 = 1.f / l_i[0], inv1 = 1.f / l_i[1];
    int row_g = b * SEQ + q0 + r0;
    #pragma unroll
    for (int na = 0; na < 8; na++) {
        int col = h * HD + na * 8 + 2 * t;
        float2 o0 = { o[na][0] * inv0, o[na][1] * inv0 };
        *(float2*)(g_ctx + (size_t)row_g * EMB + col) = o0;
        float2 o1 = { o[na][2] * inv1, o[na][3] * inv1 };
        *(float2*)(g_ctx + (size_t)(row_g + 8) * EMB + col) = o1;
    }
}

// ---------------------------------------------------------------------------
extern "C" void kernel_launch(void* const* d_in, const int* in_sizes, int n_in,
                              void* d_out, int out_size)
{
    (void)in_sizes; (void)n_in; (void)out_size;
    const float* qkv   = (const float*)d_in[0];
    const float* w_in  = (const float*)d_in[1];
    const float* b_in  = (const float*)d_in[2];
    const float* w_out = (const float*)d_in[3];
    const float* b_out = (const float*)d_in[4];
    float* out = (float*)d_out;

    int gemm_smem = 4 * 128 * TSH * sizeof(__half);   // 40960
    int attn_smem = 384 * AST * sizeof(float);        // 104448
    cudaFuncSetAttribute(gemm_f16, cudaFuncAttributeMaxDynamicSharedMemorySize, gemm_smem);
    cudaFuncSetAttribute(attn_tf32, cudaFuncAttributeMaxDynamicSharedMemorySize, attn_smem);

    dim3 g1(3 * EMB / 128, TOK / 128);
    gemm_f16<<<g1, 256, gemm_smem>>>(qkv, w_in, b_in, nullptr, 3 * EMB, EMB, 0);

    dim3 g2(SEQ / 128, NH, BATCH);
    attn_tf32<<<g2, 256, attn_smem>>>();

    dim3 g3(EMB / 128, TOK / 128);
    gemm_f16<<<g3, 256, gemm_smem>>>(nullptr, w_out, b_out, out, EMB, EMB, 1);
}

// round 9
// speedup vs baseline: 4.7869x; 1.3569x over previous
#include <cuda_runtime.h>
#include <cuda_fp16.h>
#include <math.h>
#include <stdint.h>

#define EMB   1024
#define SEQ   1024
#define BATCH 8
#define NH    16
#define HD    64
#define TOK   (BATCH*SEQ)   // 8192

// Scratch
__device__ float g_proj[(size_t)TOK * 3 * EMB];  // q|k|v per token
__device__ float g_ctx[(size_t)TOK * EMB];       // attention output

// ---------------------------------------------------------------------------
__device__ __forceinline__ float ex2(float x) {
    float y; asm("ex2.approx.ftz.f32 %0, %1;" : "=f"(y) : "f"(x)); return y;
}
__device__ __forceinline__ uint32_t s2u(const void* p) {
    return (uint32_t)__cvta_generic_to_shared(p);
}
__device__ __forceinline__ void mma_f16(float c[4], const unsigned a[4],
                                        unsigned b0, unsigned b1) {
    asm volatile(
        "mma.sync.aligned.m16n8k16.row.col.f32.f16.f16.f32 "
        "{%0,%1,%2,%3}, {%4,%5,%6,%7}, {%8,%9}, {%0,%1,%2,%3};"
        : "+f"(c[0]), "+f"(c[1]), "+f"(c[2]), "+f"(c[3])
        : "r"(a[0]), "r"(a[1]), "r"(a[2]), "r"(a[3]), "r"(b0), "r"(b1));
}
__device__ __forceinline__ void ldsm_x4(unsigned r[4], uint32_t addr) {
    asm volatile("ldmatrix.sync.aligned.m8n8.x4.shared.b16 {%0,%1,%2,%3}, [%4];"
        : "=r"(r[0]), "=r"(r[1]), "=r"(r[2]), "=r"(r[3]) : "r"(addr));
}
__device__ __forceinline__ void ldsm_x4_t(unsigned r[4], uint32_t addr) {
    asm volatile("ldmatrix.sync.aligned.m8n8.x4.trans.shared.b16 {%0,%1,%2,%3}, [%4];"
        : "=r"(r[0]), "=r"(r[1]), "=r"(r[2]), "=r"(r[3]) : "r"(addr));
}
__device__ __forceinline__ unsigned packh2(float a, float b) {
    __half2 h = __floats2half2_rn(a, b);
    return *(unsigned*)&h;
}

// ---------------------------------------------------------------------------
// GEMM — unchanged from Round 8 (passing).
// ---------------------------------------------------------------------------
#define BK  32
#define TSH 40

__global__ __launch_bounds__(256, 2) void gemm_f16(
    const float* __restrict__ Aext,
    const float* __restrict__ Bw,
    const float* __restrict__ bias,
    float* __restrict__ Cext,
    int N, int K, int mode)
{
    const float* A = (mode == 0) ? Aext : g_ctx;
    float*       C = (mode == 0) ? g_proj : Cext;

    extern __shared__ __half smh[];
    __half* Abuf0 = smh;
    __half* Abuf1 = smh + 128 * TSH;
    __half* Bbuf0 = smh + 2 * 128 * TSH;
    __half* Bbuf1 = smh + 3 * 128 * TSH;

    int tid  = threadIdx.x;
    int lane = tid & 31, w = tid >> 5;
    int g = lane >> 2, t = lane & 3;
    int wm = (w >> 1) * 32, wn = (w & 1) * 64;
    int bm = blockIdx.y * 128, bn = blockIdx.x * 128;

    int lr = tid >> 3;
    int lc = (tid & 7) * 4;

    const float* Ap = A  + (size_t)(bm + lr) * K + lc;
    const float* Bp = Bw + (size_t)(bn + lr) * K + lc;

    int a_off = (wm + (lane & 15)) * TSH * 2 + (lane >> 4) * 16;
    int b_off = (wn + (lane & 7) + 8 * (lane >> 4)) * TSH * 2 + ((lane >> 3) & 1) * 16;

    float4 ra[4], rb[4];

    auto LDG = [&](int chunk) {
        const float* ap = Ap + chunk * BK;
        const float* bp = Bp + chunk * BK;
        #pragma unroll
        for (int i = 0; i < 4; i++) {
            ra[i] = *(const float4*)(ap + (size_t)(32 * i) * K);
            rb[i] = *(const float4*)(bp + (size_t)(32 * i) * K);
        }
    };
    auto STS = [&](__half* as, __half* bs) {
        #pragma unroll
        for (int i = 0; i < 4; i++) {
            int r = lr + 32 * i;
            uint2 av = { packh2(ra[i].x, ra[i].y), packh2(ra[i].z, ra[i].w) };
            *(uint2*)(as + r * TSH + lc) = av;
            uint2 bv = { packh2(rb[i].x, rb[i].y), packh2(rb[i].z, rb[i].w) };
            *(uint2*)(bs + r * TSH + lc) = bv;
        }
    };

    float acc[2][8][4];
    #pragma unroll
    for (int ma = 0; ma < 2; ma++)
        #pragma unroll
        for (int na = 0; na < 8; na++)
            #pragma unroll
            for (int j = 0; j < 4; j++) acc[ma][na][j] = 0.f;

    auto COMPUTE = [&](const __half* as, const __half* bs) {
        uint32_t abase = s2u(as) + a_off;
        uint32_t bbase = s2u(bs) + b_off;
        #pragma unroll
        for (int s = 0; s < 2; s++) {
            uint32_t ko = s * 32;
            unsigned af[2][4];
            ldsm_x4(af[0], abase + ko);
            ldsm_x4(af[1], abase + 16 * TSH * 2 + ko);
            #pragma unroll
            for (int j = 0; j < 4; j++) {
                unsigned bf[4];
                ldsm_x4(bf, bbase + j * 16 * TSH * 2 + ko);
                #pragma unroll
                for (int ma = 0; ma < 2; ma++) {
                    mma_f16(acc[ma][2 * j],     af[ma], bf[0], bf[1]);
                    mma_f16(acc[ma][2 * j + 1], af[ma], bf[2], bf[3]);
                }
            }
        }
    };

    int nch = K / BK;
    LDG(0);
    STS(Abuf0, Bbuf0);
    LDG(1);
    __syncthreads();

    for (int i = 0; i < nch; i++) {
        int cur = i & 1;
        if (i + 1 < nch) {
            if (cur) STS(Abuf0, Bbuf0); else STS(Abuf1, Bbuf1);
        }
        if (i + 2 < nch) LDG(i + 2);
        if (cur) COMPUTE(Abuf1, Bbuf1); else COMPUTE(Abuf0, Bbuf0);
        __syncthreads();
    }

    #pragma unroll
    for (int ma = 0; ma < 2; ma++) {
        int r0 = bm + wm + ma * 16 + g;
        #pragma unroll
        for (int na = 0; na < 8; na++) {
            int col = bn + wn + na * 8 + 2 * t;
            float2 bv = *(const float2*)(bias + col);
            float2 o0 = { acc[ma][na][0] + bv.x, acc[ma][na][1] + bv.y };
            *(float2*)(C + (size_t)r0 * N + col) = o0;
            float2 o1 = { acc[ma][na][2] + bv.x, acc[ma][na][3] + bv.y };
            *(float2*)(C + (size_t)(r0 + 8) * N + col) = o1;
        }
    }
}

// ---------------------------------------------------------------------------
// Flash attention, all-fp16 operands (f32 accum). CTA = (b, h, 128-q block),
// 256 threads. S = QK^T via fp16 MMA (A/B ldmatrix patterns validated in the
// R8 GEMM). P through smem as fp16 (A-frag). V natural [key][d] layout, B-frag
// via ldmatrix.x4.trans (FlashAttention-2 pattern).
// ---------------------------------------------------------------------------
#define QST 72   // halves per row (144 B; rows 16B-aligned, ldsm conflict-free)

__global__ __launch_bounds__(256) void attn_f16()
{
    extern __shared__ __half sma[];
    __half* Qs = sma;                // [128][QST]
    __half* Ks = sma + 128 * QST;    // [64][QST]
    __half* Vs = sma + 192 * QST;    // [64][QST]  (natural [key][d])
    __half* Ps = sma + 256 * QST;    // [128][QST] ([row][key])

    int tid = threadIdx.x, lane = tid & 31, w = tid >> 5;
    int g = lane >> 2, t = lane & 3;
    int h = blockIdx.y, b = blockIdx.z, q0 = blockIdx.x * 128;

    const float* base = g_proj + (size_t)b * SEQ * (3 * EMB) + h * HD;
    const float SCL = 0.125f * 1.4426950408889634f;   // 1/sqrt(64) * log2(e)

    // Fragment per-lane byte offsets:
    int aoff = (w * 16 + (lane & 15)) * QST * 2 + (lane >> 4) * 16;     // A-style (Q/P)
    int boff = ((lane & 7) + 8 * (lane >> 4)) * QST * 2 + ((lane >> 3) & 1) * 16; // B-style (K)
    int voff = ((lane & 7) + 8 * ((lane >> 3) & 1)) * QST + 8 * (lane >> 4);      // V trans (halves)
    uint32_t qbase = s2u(Qs) + aoff;
    uint32_t pbase = s2u(Ps) + aoff;
    uint32_t kbase = s2u(Ks) + boff;
    uint32_t vbase = s2u(Vs) + voff * 2;

    // Stage Q (scale by SCL, fp16)
    {
        int r = tid >> 1, cb = (tid & 1) * 32;
        const float* src = base + (size_t)(q0 + r) * (3 * EMB) + cb;
        __half* dst = Qs + r * QST + cb;
        #pragma unroll
        for (int i = 0; i < 8; i++) {
            float4 v = *(const float4*)(src + i * 4);
            uint2 hv = { packh2(v.x * SCL, v.y * SCL), packh2(v.z * SCL, v.w * SCL) };
            *(uint2*)(dst + i * 4) = hv;
        }
    }

    float m_i[2] = { -1e30f, -1e30f }, l_i[2] = { 0.f, 0.f };
    float o[8][4];
    #pragma unroll
    for (int na = 0; na < 8; na++)
        #pragma unroll
        for (int j = 0; j < 4; j++) o[na][j] = 0.f;

    int r0 = w * 16 + g;

    for (int kb = 0; kb < 16; kb++) {
        __syncthreads();
        // Stage K and V (fp16)
        {
            int r = tid >> 2, cb = (tid & 3) * 16;
            const float* ksrc = base + EMB     + (size_t)(kb * 64 + r) * (3 * EMB) + cb;
            const float* vsrc = base + 2 * EMB + (size_t)(kb * 64 + r) * (3 * EMB) + cb;
            __half* kd = Ks + r * QST + cb;
            __half* vd = Vs + r * QST + cb;
            #pragma unroll
            for (int i = 0; i < 4; i++) {
                float4 kv = *(const float4*)(ksrc + i * 4);
                uint2 kh = { packh2(kv.x, kv.y), packh2(kv.z, kv.w) };
                *(uint2*)(kd + i * 4) = kh;
                float4 vv = *(const float4*)(vsrc + i * 4);
                uint2 vh = { packh2(vv.x, vv.y), packh2(vv.z, vv.w) };
                *(uint2*)(vd + i * 4) = vh;
            }
        }
        __syncthreads();

        // S = Q K^T (warp m16 x n64, k=64; 4 k16 steps)
        float sc[8][4];
        #pragma unroll
        for (int na = 0; na < 8; na++)
            #pragma unroll
            for (int j = 0; j < 4; j++) sc[na][j] = 0.f;

        #pragma unroll
        for (int ks = 0; ks < 4; ks++) {
            uint32_t ko = ks * 32;   // 16 halves
            unsigned af[4];
            ldsm_x4(af, qbase + ko);
            #pragma unroll
            for (int j = 0; j < 4; j++) {
                unsigned bf[4];
                ldsm_x4(bf, kbase + j * 16 * QST * 2 + ko);
                mma_f16(sc[2 * j],     af, bf[0], bf[1]);
                mma_f16(sc[2 * j + 1], af, bf[2], bf[3]);
            }
        }

        // Online softmax (exp2 domain); P -> smem fp16
        #pragma unroll
        for (int half = 0; half < 2; half++) {
            float rm = -1e30f;
            #pragma unroll
            for (int na = 0; na < 8; na++)
                rm = fmaxf(rm, fmaxf(sc[na][half*2], sc[na][half*2+1]));
            rm = fmaxf(rm, __shfl_xor_sync(0xffffffffu, rm, 1));
            rm = fmaxf(rm, __shfl_xor_sync(0xffffffffu, rm, 2));
            float mn = fmaxf(m_i[half], rm);
            float al = ex2(m_i[half] - mn);
            float rs = 0.f;
            int prow = w * 16 + half * 8 + g;
            #pragma unroll
            for (int na = 0; na < 8; na++) {
                float p0 = ex2(sc[na][half*2]   - mn);
                float p1 = ex2(sc[na][half*2+1] - mn);
                rs += p0 + p1;
                *(unsigned*)(Ps + prow * QST + na * 8 + 2 * t) = packh2(p0, p1);
                o[na][half*2]   *= al;
                o[na][half*2+1] *= al;
            }
            rs += __shfl_xor_sync(0xffffffffu, rs, 1);
            rs += __shfl_xor_sync(0xffffffffu, rs, 2);
            l_i[half] = l_i[half] * al + rs;
            m_i[half] = mn;
        }
        __syncwarp();   // P rows are warp-private

        // O += P V (4 k16 steps; P A-frag, V B-frag via ldmatrix.trans)
        #pragma unroll
        for (int ks = 0; ks < 4; ks++) {
            unsigned af[4];
            ldsm_x4(af, pbase + ks * 32);
            #pragma unroll
            for (int j = 0; j < 4; j++) {
                unsigned bf[4];
                ldsm_x4_t(bf, vbase + (ks * 16 * QST + j * 16) * 2);
                mma_f16(o[2 * j],     af, bf[0], bf[1]);
                mma_f16(o[2 * j + 1], af, bf[2], bf[3]);
            }
        }
    }

    // Epilogue
    float inv0 = 1.f / l_i[0], inv1 = 1.f / l_i[1];
    int row_g = b * SEQ + q0 + r0;
    #pragma unroll
    for (int na = 0; na < 8; na++) {
        int col = h * HD + na * 8 + 2 * t;
        float2 o0 = { o[na][0] * inv0, o[na][1] * inv0 };
        *(float2*)(g_ctx + (size_t)row_g * EMB + col) = o0;
        float2 o1 = { o[na][2] * inv1, o[na][3] * inv1 };
        *(float2*)(g_ctx + (size_t)(row_g + 8) * EMB + col) = o1;
    }
}

// ---------------------------------------------------------------------------
extern "C" void kernel_launch(void* const* d_in, const int* in_sizes, int n_in,
                              void* d_out, int out_size)
{
    (void)in_sizes; (void)n_in; (void)out_size;
    const float* qkv   = (const float*)d_in[0];
    const float* w_in  = (const float*)d_in[1];
    const float* b_in  = (const float*)d_in[2];
    const float* w_out = (const float*)d_in[3];
    const float* b_out = (const float*)d_in[4];
    float* out = (float*)d_out;

    int gemm_smem = 4 * 128 * TSH * sizeof(__half);   // 40960
    int attn_smem = 384 * QST * sizeof(__half);       // 55296
    cudaFuncSetAttribute(gemm_f16, cudaFuncAttributeMaxDynamicSharedMemorySize, gemm_smem);
    cudaFuncSetAttribute(attn_f16, cudaFuncAttributeMaxDynamicSharedMemorySize, attn_smem);

    dim3 g1(3 * EMB / 128, TOK / 128);
    gemm_f16<<<g1, 256, gemm_smem>>>(qkv, w_in, b_in, nullptr, 3 * EMB, EMB, 0);

    dim3 g2(SEQ / 128, NH, BATCH);
    attn_f16<<<g2, 256, attn_smem>>>();

    dim3 g3(EMB / 128, TOK / 128);
    gemm_f16<<<g3, 256, gemm_smem>>>(nullptr, w_out, b_out, out, EMB, EMB, 1);
}

// round 10
// speedup vs baseline: 5.9359x; 1.2400x over previous
#include <cuda_runtime.h>
#include <cuda_fp16.h>
#include <math.h>
#include <stdint.h>

#define EMB   1024
#define SEQ   1024
#define BATCH 8
#define NH    16
#define HD    64
#define TOK   (BATCH*SEQ)   // 8192

// Scratch — fp16 intermediates
__device__ __half g_proj[(size_t)TOK * 3 * EMB];  // q|k|v per token (fp16)
__device__ __half g_ctx[(size_t)TOK * EMB];       // attention output (fp16)

// ---------------------------------------------------------------------------
__device__ __forceinline__ float ex2(float x) {
    float y; asm("ex2.approx.ftz.f32 %0, %1;" : "=f"(y) : "f"(x)); return y;
}
__device__ __forceinline__ uint32_t s2u(const void* p) {
    return (uint32_t)__cvta_generic_to_shared(p);
}
__device__ __forceinline__ void mma_f16(float c[4], const unsigned a[4],
                                        unsigned b0, unsigned b1) {
    asm volatile(
        "mma.sync.aligned.m16n8k16.row.col.f32.f16.f16.f32 "
        "{%0,%1,%2,%3}, {%4,%5,%6,%7}, {%8,%9}, {%0,%1,%2,%3};"
        : "+f"(c[0]), "+f"(c[1]), "+f"(c[2]), "+f"(c[3])
        : "r"(a[0]), "r"(a[1]), "r"(a[2]), "r"(a[3]), "r"(b0), "r"(b1));
}
__device__ __forceinline__ void ldsm_x4(unsigned r[4], uint32_t addr) {
    asm volatile("ldmatrix.sync.aligned.m8n8.x4.shared.b16 {%0,%1,%2,%3}, [%4];"
        : "=r"(r[0]), "=r"(r[1]), "=r"(r[2]), "=r"(r[3]) : "r"(addr));
}
__device__ __forceinline__ void ldsm_x4_t(unsigned r[4], uint32_t addr) {
    asm volatile("ldmatrix.sync.aligned.m8n8.x4.trans.shared.b16 {%0,%1,%2,%3}, [%4];"
        : "=r"(r[0]), "=r"(r[1]), "=r"(r[2]), "=r"(r[3]) : "r"(addr));
}
__device__ __forceinline__ unsigned packh2(float a, float b) {
    __half2 h = __floats2half2_rn(a, b);
    return *(unsigned*)&h;
}

// ---------------------------------------------------------------------------
// GEMM: C[m][n] = bias[n] + sum_k A[m][k] * W[n][k]   (x @ W^T + b)
// MODE 0: A = Aext (f32), C = g_proj (fp16).  MODE 1: A = g_ctx (fp16), C f32.
// ---------------------------------------------------------------------------
#define BK  32
#define TSH 40

template<int MODE>
__global__ __launch_bounds__(256, 2) void gemm_f16(
    const float* __restrict__ Aext,
    const float* __restrict__ Bw,
    const float* __restrict__ bias,
    float* __restrict__ Cext,
    int N, int K)
{
    extern __shared__ __half smh[];
    __half* Abuf0 = smh;
    __half* Abuf1 = smh + 128 * TSH;
    __half* Bbuf0 = smh + 2 * 128 * TSH;
    __half* Bbuf1 = smh + 3 * 128 * TSH;

    int tid  = threadIdx.x;
    int lane = tid & 31, w = tid >> 5;
    int g = lane >> 2, t = lane & 3;
    int wm = (w >> 1) * 32, wn = (w & 1) * 64;
    int bm = blockIdx.y * 128, bn = blockIdx.x * 128;

    int lr = tid >> 3;        // 0..31
    int lc = (tid & 7) * 4;   // 0..28

    const float*  ApF = Aext  + (size_t)(bm + lr) * K + lc;
    const __half* ApH = g_ctx + (size_t)(bm + lr) * K + lc;
    const float*  Bp  = Bw    + (size_t)(bn + lr) * K + lc;

    int a_off = (wm + (lane & 15)) * TSH * 2 + (lane >> 4) * 16;
    int b_off = (wn + (lane & 7) + 8 * (lane >> 4)) * TSH * 2 + ((lane >> 3) & 1) * 16;

    float4 ra[4], rb[4];
    uint2  rah[4];

    auto LDG = [&](int chunk) {
        #pragma unroll
        for (int i = 0; i < 4; i++) {
            if (MODE == 0)
                ra[i]  = *(const float4*)(ApF + chunk * BK + (size_t)(32 * i) * K);
            else
                rah[i] = *(const uint2*)(ApH + chunk * BK + (size_t)(32 * i) * K);
            rb[i] = *(const float4*)(Bp + chunk * BK + (size_t)(32 * i) * K);
        }
    };
    auto STS = [&](__half* as, __half* bs) {
        #pragma unroll
        for (int i = 0; i < 4; i++) {
            int r = lr + 32 * i;
            if (MODE == 0) {
                uint2 av = { packh2(ra[i].x, ra[i].y), packh2(ra[i].z, ra[i].w) };
                *(uint2*)(as + r * TSH + lc) = av;
            } else {
                *(uint2*)(as + r * TSH + lc) = rah[i];
            }
            uint2 bv = { packh2(rb[i].x, rb[i].y), packh2(rb[i].z, rb[i].w) };
            *(uint2*)(bs + r * TSH + lc) = bv;
        }
    };

    float acc[2][8][4];
    #pragma unroll
    for (int ma = 0; ma < 2; ma++)
        #pragma unroll
        for (int na = 0; na < 8; na++)
            #pragma unroll
            for (int j = 0; j < 4; j++) acc[ma][na][j] = 0.f;

    auto COMPUTE = [&](const __half* as, const __half* bs) {
        uint32_t abase = s2u(as) + a_off;
        uint32_t bbase = s2u(bs) + b_off;
        #pragma unroll
        for (int s = 0; s < 2; s++) {
            uint32_t ko = s * 32;
            unsigned af[2][4];
            ldsm_x4(af[0], abase + ko);
            ldsm_x4(af[1], abase + 16 * TSH * 2 + ko);
            #pragma unroll
            for (int j = 0; j < 4; j++) {
                unsigned bf[4];
                ldsm_x4(bf, bbase + j * 16 * TSH * 2 + ko);
                #pragma unroll
                for (int ma = 0; ma < 2; ma++) {
                    mma_f16(acc[ma][2 * j],     af[ma], bf[0], bf[1]);
                    mma_f16(acc[ma][2 * j + 1], af[ma], bf[2], bf[3]);
                }
            }
        }
    };

    int nch = K / BK;
    LDG(0);
    STS(Abuf0, Bbuf0);
    LDG(1);
    __syncthreads();

    for (int i = 0; i < nch; i++) {
        int cur = i & 1;
        if (i + 1 < nch) {
            if (cur) STS(Abuf0, Bbuf0); else STS(Abuf1, Bbuf1);
        }
        if (i + 2 < nch) LDG(i + 2);
        if (cur) COMPUTE(Abuf1, Bbuf1); else COMPUTE(Abuf0, Bbuf0);
        __syncthreads();
    }

    #pragma unroll
    for (int ma = 0; ma < 2; ma++) {
        int r0 = bm + wm + ma * 16 + g;
        #pragma unroll
        for (int na = 0; na < 8; na++) {
            int col = bn + wn + na * 8 + 2 * t;
            float2 bv = *(const float2*)(bias + col);
            if (MODE == 0) {
                *(unsigned*)(g_proj + (size_t)r0 * N + col) =
                    packh2(acc[ma][na][0] + bv.x, acc[ma][na][1] + bv.y);
                *(unsigned*)(g_proj + (size_t)(r0 + 8) * N + col) =
                    packh2(acc[ma][na][2] + bv.x, acc[ma][na][3] + bv.y);
            } else {
                float2 o0 = { acc[ma][na][0] + bv.x, acc[ma][na][1] + bv.y };
                *(float2*)(Cext + (size_t)r0 * N + col) = o0;
                float2 o1 = { acc[ma][na][2] + bv.x, acc[ma][na][3] + bv.y };
                *(float2*)(Cext + (size_t)(r0 + 8) * N + col) = o1;
            }
        }
    }
}

// ---------------------------------------------------------------------------
// Flash attention, all fp16, register-resident P. CTA = (b, h, 128-q block),
// 256 threads. S via fp16 MMA (R9-validated frags); P packed straight from
// the S accumulator into A-fragments (no smem round-trip); V via ldsm.trans.
// ---------------------------------------------------------------------------
#define QST 72   // halves per row (144 B)

__global__ __launch_bounds__(256, 2) void attn_f16()
{
    extern __shared__ __half sma[];
    __half* Qs = sma;                // [128][QST]
    __half* Ks = sma + 128 * QST;    // [64][QST]
    __half* Vs = sma + 192 * QST;    // [64][QST]  natural [key][d]

    int tid = threadIdx.x, lane = tid & 31, w = tid >> 5;
    int g = lane >> 2, t = lane & 3;
    int h = blockIdx.y, b = blockIdx.z, q0 = blockIdx.x * 128;

    const __half* base = g_proj + (size_t)b * SEQ * (3 * EMB) + h * HD;
    const float SCL = 0.125f * 1.4426950408889634f;
    const __half2 SCL2 = __float2half2_rn(SCL);

    int aoff = (w * 16 + (lane & 15)) * QST * 2 + (lane >> 4) * 16;               // A-style (Q)
    int boff = ((lane & 7) + 8 * (lane >> 4)) * QST * 2 + ((lane >> 3) & 1) * 16; // B-style (K)
    int voff = ((lane & 7) + 8 * ((lane >> 3) & 1)) * QST + 8 * (lane >> 4);      // V trans (halves)
    uint32_t qbase = s2u(Qs) + aoff;
    uint32_t kbase = s2u(Ks) + boff;
    uint32_t vbase = s2u(Vs) + voff * 2;

    // Stage Q (fp16 source, scale by SCL)
    {
        int r = tid >> 1, cb = (tid & 1) * 32;
        const uint4* src = (const uint4*)(base + (size_t)(q0 + r) * (3 * EMB) + cb);
        uint4* dst = (uint4*)(Qs + r * QST + cb);
        #pragma unroll
        for (int i = 0; i < 4; i++) {
            uint4 v = src[i];
            __half2* hv = (__half2*)&v;
            #pragma unroll
            for (int j = 0; j < 4; j++) hv[j] = __hmul2(hv[j], SCL2);
            dst[i] = v;
        }
    }

    float m_i[2] = { -1e30f, -1e30f }, l_i[2] = { 0.f, 0.f };
    float o[8][4];
    #pragma unroll
    for (int na = 0; na < 8; na++)
        #pragma unroll
        for (int j = 0; j < 4; j++) o[na][j] = 0.f;

    int r0 = w * 16 + g;

    for (int kb = 0; kb < 16; kb++) {
        __syncthreads();   // prior-iter ldsm reads of Ks/Vs done; Q ready on kb=0
        // Stage K and V (fp16, direct copies)
        {
            int r = tid >> 2, cb = (tid & 3) * 16;
            const uint4* ks4 = (const uint4*)(base + EMB     + (size_t)(kb * 64 + r) * (3 * EMB) + cb);
            const uint4* vs4 = (const uint4*)(base + 2 * EMB + (size_t)(kb * 64 + r) * (3 * EMB) + cb);
            uint4* kd = (uint4*)(Ks + r * QST + cb);
            uint4* vd = (uint4*)(Vs + r * QST + cb);
            kd[0] = ks4[0]; kd[1] = ks4[1];
            vd[0] = vs4[0]; vd[1] = vs4[1];
        }
        __syncthreads();

        // S = Q K^T (warp m16 x n64, 4 k16 steps)
        float sc[8][4];
        #pragma unroll
        for (int na = 0; na < 8; na++)
            #pragma unroll
            for (int j = 0; j < 4; j++) sc[na][j] = 0.f;

        #pragma unroll
        for (int ks = 0; ks < 4; ks++) {
            uint32_t ko = ks * 32;
            unsigned af[4];
            ldsm_x4(af, qbase + ko);
            #pragma unroll
            for (int j = 0; j < 4; j++) {
                unsigned bf[4];
                ldsm_x4(bf, kbase + j * 16 * QST * 2 + ko);
                mma_f16(sc[2 * j],     af, bf[0], bf[1]);
                mma_f16(sc[2 * j + 1], af, bf[2], bf[3]);
            }
        }

        // Online softmax (exp2 domain); P packed into registers as half2
        unsigned h2lo[8], h2hi[8];   // h2lo[na]=(row g, cols 2t,2t+1); h2hi=(row g+8)
        {
            float rm = -1e30f;
            #pragma unroll
            for (int na = 0; na < 8; na++)
                rm = fmaxf(rm, fmaxf(sc[na][0], sc[na][1]));
            rm = fmaxf(rm, __shfl_xor_sync(0xffffffffu, rm, 1));
            rm = fmaxf(rm, __shfl_xor_sync(0xffffffffu, rm, 2));
            float mn = fmaxf(m_i[0], rm);
            float al = ex2(m_i[0] - mn);
            float rs = 0.f;
            #pragma unroll
            for (int na = 0; na < 8; na++) {
                float p0 = ex2(sc[na][0] - mn);
                float p1 = ex2(sc[na][1] - mn);
                rs += p0 + p1;
                h2lo[na] = packh2(p0, p1);
                o[na][0] *= al; o[na][1] *= al;
            }
            rs += __shfl_xor_sync(0xffffffffu, rs, 1);
            rs += __shfl_xor_sync(0xffffffffu, rs, 2);
            l_i[0] = l_i[0] * al + rs; m_i[0] = mn;
        }
        {
            float rm = -1e30f;
            #pragma unroll
            for (int na = 0; na < 8; na++)
                rm = fmaxf(rm, fmaxf(sc[na][2], sc[na][3]));
            rm = fmaxf(rm, __shfl_xor_sync(0xffffffffu, rm, 1));
            rm = fmaxf(rm, __shfl_xor_sync(0xffffffffu, rm, 2));
            float mn = fmaxf(m_i[1], rm);
            float al = ex2(m_i[1] - mn);
            float rs = 0.f;
            #pragma unroll
            for (int na = 0; na < 8; na++) {
                float p0 = ex2(sc[na][2] - mn);
                float p1 = ex2(sc[na][3] - mn);
                rs += p0 + p1;
                h2hi[na] = packh2(p0, p1);
                o[na][2] *= al; o[na][3] *= al;
            }
            rs += __shfl_xor_sync(0xffffffffu, rs, 1);
            rs += __shfl_xor_sync(0xffffffffu, rs, 2);
            l_i[1] = l_i[1] * al + rs; m_i[1] = mn;
        }

        // O += P V  (P from registers; V B-frag via ldsm.trans)
        #pragma unroll
        for (int ks = 0; ks < 4; ks++) {
            unsigned af[4] = { h2lo[2 * ks], h2hi[2 * ks],
                               h2lo[2 * ks + 1], h2hi[2 * ks + 1] };
            #pragma unroll
            for (int j = 0; j < 4; j++) {
                unsigned bf[4];
                ldsm_x4_t(bf, vbase + (ks * 16 * QST + j * 16) * 2);
                mma_f16(o[2 * j],     af, bf[0], bf[1]);
                mma_f16(o[2 * j + 1], af, bf[2], bf[3]);
            }
        }
    }

    // Epilogue -> g_ctx (fp16)
    float inv0 = 1.f / l_i[0], inv1 = 1.f / l_i[1];
    int row_g = b * SEQ + q0 + r0;
    __half* orow0 = g_ctx + (size_t)row_g * EMB + h * HD;
    __half* orow1 = orow0 + (size_t)8 * EMB;
    #pragma unroll
    for (int na = 0; na < 8; na++) {
        int col = na * 8 + 2 * t;
        *(unsigned*)(orow0 + col) = packh2(o[na][0] * inv0, o[na][1] * inv0);
        *(unsigned*)(orow1 + col) = packh2(o[na][2] * inv1, o[na][3] * inv1);
    }
}

// ---------------------------------------------------------------------------
extern "C" void kernel_launch(void* const* d_in, const int* in_sizes, int n_in,
                              void* d_out, int out_size)
{
    (void)in_sizes; (void)n_in; (void)out_size;
    const float* qkv   = (const float*)d_in[0];
    const float* w_in  = (const float*)d_in[1];
    const float* b_in  = (const float*)d_in[2];
    const float* w_out = (const float*)d_in[3];
    const float* b_out = (const float*)d_in[4];
    float* out = (float*)d_out;

    int gemm_smem = 4 * 128 * TSH * sizeof(__half);   // 40960
    int attn_smem = 256 * QST * sizeof(__half);       // 36864
    cudaFuncSetAttribute(gemm_f16<0>, cudaFuncAttributeMaxDynamicSharedMemorySize, gemm_smem);
    cudaFuncSetAttribute(gemm_f16<1>, cudaFuncAttributeMaxDynamicSharedMemorySize, gemm_smem);
    cudaFuncSetAttribute(attn_f16, cudaFuncAttributeMaxDynamicSharedMemorySize, attn_smem);

    dim3 g1(3 * EMB / 128, TOK / 128);
    gemm_f16<0><<<g1, 256, gemm_smem>>>(qkv, w_in, b_in, nullptr, 3 * EMB, EMB);

    dim3 g2(SEQ / 128, NH, BATCH);
    attn_f16<<<g2, 256, attn_smem>>>();

    dim3 g3(EMB / 128, TOK / 128);
    gemm_f16<1><<<g3, 256, gemm_smem>>>(nullptr, w_out, b_out, out, EMB, EMB);
}

// round 11
// speedup vs baseline: 6.0676x; 1.0222x over previous
#include <cuda_runtime.h>
#include <cuda_fp16.h>
#include <math.h>
#include <stdint.h>

#define EMB   1024
#define SEQ   1024
#define BATCH 8
#define NH    16
#define HD    64
#define TOK   (BATCH*SEQ)   // 8192

// Scratch — fp16 everywhere
__device__ __half g_qkv16[(size_t)TOK * EMB];       // input, fp16
__device__ __half g_win16[(size_t)3 * EMB * EMB];   // W_in, fp16
__device__ __half g_wout16[(size_t)EMB * EMB];      // W_out, fp16
__device__ __half g_proj[(size_t)TOK * 3 * EMB];    // q|k|v per token
__device__ __half g_ctx[(size_t)TOK * EMB];         // attention output

// ---------------------------------------------------------------------------
__device__ __forceinline__ float ex2(float x) {
    float y; asm("ex2.approx.ftz.f32 %0, %1;" : "=f"(y) : "f"(x)); return y;
}
__device__ __forceinline__ uint32_t s2u(const void* p) {
    return (uint32_t)__cvta_generic_to_shared(p);
}
__device__ __forceinline__ void mma_f16(float c[4], const unsigned a[4],
                                        unsigned b0, unsigned b1) {
    asm volatile(
        "mma.sync.aligned.m16n8k16.row.col.f32.f16.f16.f32 "
        "{%0,%1,%2,%3}, {%4,%5,%6,%7}, {%8,%9}, {%0,%1,%2,%3};"
        : "+f"(c[0]), "+f"(c[1]), "+f"(c[2]), "+f"(c[3])
        : "r"(a[0]), "r"(a[1]), "r"(a[2]), "r"(a[3]), "r"(b0), "r"(b1));
}
__device__ __forceinline__ void ldsm_x4(unsigned r[4], uint32_t addr) {
    asm volatile("ldmatrix.sync.aligned.m8n8.x4.shared.b16 {%0,%1,%2,%3}, [%4];"
        : "=r"(r[0]), "=r"(r[1]), "=r"(r[2]), "=r"(r[3]) : "r"(addr));
}
__device__ __forceinline__ void ldsm_x4_t(unsigned r[4], uint32_t addr) {
    asm volatile("ldmatrix.sync.aligned.m8n8.x4.trans.shared.b16 {%0,%1,%2,%3}, [%4];"
        : "=r"(r[0]), "=r"(r[1]), "=r"(r[2]), "=r"(r[3]) : "r"(addr));
}
__device__ __forceinline__ unsigned packh2(float a, float b) {
    __half2 h = __floats2half2_rn(a, b);
    return *(unsigned*)&h;
}

// ---------------------------------------------------------------------------
// Pre-pass: f32 -> fp16 elementwise (4 elems/thread)
// ---------------------------------------------------------------------------
__global__ __launch_bounds__(256) void to_half(const float4* __restrict__ src,
                                               uint2* __restrict__ dst, int n4)
{
    int i = blockIdx.x * blockDim.x + threadIdx.x;
    if (i < n4) {
        float4 v = src[i];
        uint2 o = { packh2(v.x, v.y), packh2(v.z, v.w) };
        dst[i] = o;
    }
}

// ---------------------------------------------------------------------------
// GEMM: C[m][n] = bias[n] + sum_k A[m][k] * W[n][k]   (x @ W^T + b)
// All operands fp16 at rest. MODE 0: A=g_qkv16, B=g_win16, C=g_proj (fp16).
// MODE 1: A=g_ctx, B=g_wout16, C=Cext (f32).
// ---------------------------------------------------------------------------
#define BK  32
#define TSH 40

template<int MODE>
__global__ __launch_bounds__(256, 2) void gemm_f16(
    const float* __restrict__ bias,
    float* __restrict__ Cext,
    int N, int K)
{
    extern __shared__ __half smh[];
    __half* Abuf0 = smh;
    __half* Abuf1 = smh + 128 * TSH;
    __half* Bbuf0 = smh + 2 * 128 * TSH;
    __half* Bbuf1 = smh + 3 * 128 * TSH;

    int tid  = threadIdx.x;
    int lane = tid & 31, w = tid >> 5;
    int g = lane >> 2, t = lane & 3;
    int wm = (w >> 1) * 32, wn = (w & 1) * 64;
    int bm = blockIdx.y * 128, bn = blockIdx.x * 128;

    int lr = tid >> 3;        // 0..31
    int lc = (tid & 7) * 4;   // 0..28

    const __half* Ah = (MODE == 0) ? g_qkv16 : g_ctx;
    const __half* Bh = (MODE == 0) ? g_win16 : g_wout16;
    const __half* Ap = Ah + (size_t)(bm + lr) * K + lc;
    const __half* Bp = Bh + (size_t)(bn + lr) * K + lc;

    int a_off = (wm + (lane & 15)) * TSH * 2 + (lane >> 4) * 16;
    int b_off = (wn + (lane & 7) + 8 * (lane >> 4)) * TSH * 2 + ((lane >> 3) & 1) * 16;

    uint2 rah[4], rbh[4];

    auto LDG = [&](int chunk) {
        #pragma unroll
        for (int i = 0; i < 4; i++) {
            rah[i] = *(const uint2*)(Ap + chunk * BK + (size_t)(32 * i) * K);
            rbh[i] = *(const uint2*)(Bp + chunk * BK + (size_t)(32 * i) * K);
        }
    };
    auto STS = [&](__half* as, __half* bs) {
        #pragma unroll
        for (int i = 0; i < 4; i++) {
            int r = lr + 32 * i;
            *(uint2*)(as + r * TSH + lc) = rah[i];
            *(uint2*)(bs + r * TSH + lc) = rbh[i];
        }
    };

    float acc[2][8][4];
    #pragma unroll
    for (int ma = 0; ma < 2; ma++)
        #pragma unroll
        for (int na = 0; na < 8; na++)
            #pragma unroll
            for (int j = 0; j < 4; j++) acc[ma][na][j] = 0.f;

    auto COMPUTE = [&](const __half* as, const __half* bs) {
        uint32_t abase = s2u(as) + a_off;
        uint32_t bbase = s2u(bs) + b_off;
        #pragma unroll
        for (int s = 0; s < 2; s++) {
            uint32_t ko = s * 32;
            unsigned af[2][4];
            ldsm_x4(af[0], abase + ko);
            ldsm_x4(af[1], abase + 16 * TSH * 2 + ko);
            #pragma unroll
            for (int j = 0; j < 4; j++) {
                unsigned bf[4];
                ldsm_x4(bf, bbase + j * 16 * TSH * 2 + ko);
                #pragma unroll
                for (int ma = 0; ma < 2; ma++) {
                    mma_f16(acc[ma][2 * j],     af[ma], bf[0], bf[1]);
                    mma_f16(acc[ma][2 * j + 1], af[ma], bf[2], bf[3]);
                }
            }
        }
    };

    int nch = K / BK;
    LDG(0);
    STS(Abuf0, Bbuf0);
    LDG(1);
    __syncthreads();

    for (int i = 0; i < nch; i++) {
        int cur = i & 1;
        if (i + 1 < nch) {
            if (cur) STS(Abuf0, Bbuf0); else STS(Abuf1, Bbuf1);
        }
        if (i + 2 < nch) LDG(i + 2);
        if (cur) COMPUTE(Abuf1, Bbuf1); else COMPUTE(Abuf0, Bbuf0);
        __syncthreads();
    }

    #pragma unroll
    for (int ma = 0; ma < 2; ma++) {
        int r0 = bm + wm + ma * 16 + g;
        #pragma unroll
        for (int na = 0; na < 8; na++) {
            int col = bn + wn + na * 8 + 2 * t;
            float2 bv = *(const float2*)(bias + col);
            if (MODE == 0) {
                *(unsigned*)(g_proj + (size_t)r0 * N + col) =
                    packh2(acc[ma][na][0] + bv.x, acc[ma][na][1] + bv.y);
                *(unsigned*)(g_proj + (size_t)(r0 + 8) * N + col) =
                    packh2(acc[ma][na][2] + bv.x, acc[ma][na][3] + bv.y);
            } else {
                float2 o0 = { acc[ma][na][0] + bv.x, acc[ma][na][1] + bv.y };
                *(float2*)(Cext + (size_t)r0 * N + col) = o0;
                float2 o1 = { acc[ma][na][2] + bv.x, acc[ma][na][3] + bv.y };
                *(float2*)(Cext + (size_t)(r0 + 8) * N + col) = o1;
            }
        }
    }
}

// ---------------------------------------------------------------------------
// Flash attention — R10 logic; Q fragments hoisted into registers (loaded
// once, reused across all 16 kv blocks).
// ---------------------------------------------------------------------------
#define QST 72   // halves per row (144 B)

__global__ __launch_bounds__(256, 2) void attn_f16()
{
    extern __shared__ __half sma[];
    __half* Qs = sma;                // [128][QST]
    __half* Ks = sma + 128 * QST;    // [64][QST]
    __half* Vs = sma + 192 * QST;    // [64][QST]  natural [key][d]

    int tid = threadIdx.x, lane = tid & 31, w = tid >> 5;
    int g = lane >> 2, t = lane & 3;
    int h = blockIdx.y, b = blockIdx.z, q0 = blockIdx.x * 128;

    const __half* base = g_proj + (size_t)b * SEQ * (3 * EMB) + h * HD;
    const float SCL = 0.125f * 1.4426950408889634f;
    const __half2 SCL2 = __float2half2_rn(SCL);

    int aoff = (w * 16 + (lane & 15)) * QST * 2 + (lane >> 4) * 16;
    int boff = ((lane & 7) + 8 * (lane >> 4)) * QST * 2 + ((lane >> 3) & 1) * 16;
    int voff = ((lane & 7) + 8 * ((lane >> 3) & 1)) * QST + 8 * (lane >> 4);
    uint32_t qbase = s2u(Qs) + aoff;
    uint32_t kbase = s2u(Ks) + boff;
    uint32_t vbase = s2u(Vs) + voff * 2;

    // Stage Q (fp16 source, scale by SCL)
    {
        int r = tid >> 1, cb = (tid & 1) * 32;
        const uint4* src = (const uint4*)(base + (size_t)(q0 + r) * (3 * EMB) + cb);
        uint4* dst = (uint4*)(Qs + r * QST + cb);
        #pragma unroll
        for (int i = 0; i < 4; i++) {
            uint4 v = src[i];
            __half2* hv = (__half2*)&v;
            #pragma unroll
            for (int j = 0; j < 4; j++) hv[j] = __hmul2(hv[j], SCL2);
            dst[i] = v;
        }
    }
    __syncthreads();

    // Hoist Q fragments into registers (Qs is never overwritten)
    unsigned qf[4][4];
    #pragma unroll
    for (int ks = 0; ks < 4; ks++) ldsm_x4(qf[ks], qbase + ks * 32);

    float m_i[2] = { -1e30f, -1e30f }, l_i[2] = { 0.f, 0.f };
    float o[8][4];
    #pragma unroll
    for (int na = 0; na < 8; na++)
        #pragma unroll
        for (int j = 0; j < 4; j++) o[na][j] = 0.f;

    int r0 = w * 16 + g;

    for (int kb = 0; kb < 16; kb++) {
        __syncthreads();   // prior-iter ldsm reads of Ks/Vs done
        // Stage K and V (fp16 direct copies)
        {
            int r = tid >> 2, cb = (tid & 3) * 16;
            const uint4* ks4 = (const uint4*)(base + EMB     + (size_t)(kb * 64 + r) * (3 * EMB) + cb);
            const uint4* vs4 = (const uint4*)(base + 2 * EMB + (size_t)(kb * 64 + r) * (3 * EMB) + cb);
            uint4* kd = (uint4*)(Ks + r * QST + cb);
            uint4* vd = (uint4*)(Vs + r * QST + cb);
            kd[0] = ks4[0]; kd[1] = ks4[1];
            vd[0] = vs4[0]; vd[1] = vs4[1];
        }
        __syncthreads();

        // S = Q K^T (warp m16 x n64, 4 k16 steps)
        float sc[8][4];
        #pragma unroll
        for (int na = 0; na < 8; na++)
            #pragma unroll
            for (int j = 0; j < 4; j++) sc[na][j] = 0.f;

        #pragma unroll
        for (int ks = 0; ks < 4; ks++) {
            uint32_t ko = ks * 32;
            #pragma unroll
            for (int j = 0; j < 4; j++) {
                unsigned bf[4];
                ldsm_x4(bf, kbase + j * 16 * QST * 2 + ko);
                mma_f16(sc[2 * j],     qf[ks], bf[0], bf[1]);
                mma_f16(sc[2 * j + 1], qf[ks], bf[2], bf[3]);
            }
        }

        // Online softmax (exp2 domain); P packed into registers as half2
        unsigned h2lo[8], h2hi[8];
        {
            float rm = -1e30f;
            #pragma unroll
            for (int na = 0; na < 8; na++)
                rm = fmaxf(rm, fmaxf(sc[na][0], sc[na][1]));
            rm = fmaxf(rm, __shfl_xor_sync(0xffffffffu, rm, 1));
            rm = fmaxf(rm, __shfl_xor_sync(0xffffffffu, rm, 2));
            float mn = fmaxf(m_i[0], rm);
            float al = ex2(m_i[0] - mn);
            float rs = 0.f;
            #pragma unroll
            for (int na = 0; na < 8; na++) {
                float p0 = ex2(sc[na][0] - mn);
                float p1 = ex2(sc[na][1] - mn);
                rs += p0 + p1;
                h2lo[na] = packh2(p0, p1);
                o[na][0] *= al; o[na][1] *= al;
            }
            rs += __shfl_xor_sync(0xffffffffu, rs, 1);
            rs += __shfl_xor_sync(0xffffffffu, rs, 2);
            l_i[0] = l_i[0] * al + rs; m_i[0] = mn;
        }
        {
            float rm = -1e30f;
            #pragma unroll
            for (int na = 0; na < 8; na++)
                rm = fmaxf(rm, fmaxf(sc[na][2], sc[na][3]));
            rm = fmaxf(rm, __shfl_xor_sync(0xffffffffu, rm, 1));
            rm = fmaxf(rm, __shfl_xor_sync(0xffffffffu, rm, 2));
            float mn = fmaxf(m_i[1], rm);
            float al = ex2(m_i[1] - mn);
            float rs = 0.f;
            #pragma unroll
            for (int na = 0; na < 8; na++) {
                float p0 = ex2(sc[na][2] - mn);
                float p1 = ex2(sc[na][3] - mn);
                rs += p0 + p1;
                h2hi[na] = packh2(p0, p1);
                o[na][2] *= al; o[na][3] *= al;
            }
            rs += __shfl_xor_sync(0xffffffffu, rs, 1);
            rs += __shfl_xor_sync(0xffffffffu, rs, 2);
            l_i[1] = l_i[1] * al + rs; m_i[1] = mn;
        }

        // O += P V  (P from registers; V B-frag via ldsm.trans)
        #pragma unroll
        for (int ks = 0; ks < 4; ks++) {
            unsigned af[4] = { h2lo[2 * ks], h2hi[2 * ks],
                               h2lo[2 * ks + 1], h2hi[2 * ks + 1] };
            #pragma unroll
            for (int j = 0; j < 4; j++) {
                unsigned bf[4];
                ldsm_x4_t(bf, vbase + (ks * 16 * QST + j * 16) * 2);
                mma_f16(o[2 * j],     af, bf[0], bf[1]);
                mma_f16(o[2 * j + 1], af, bf[2], bf[3]);
            }
        }
    }

    // Epilogue -> g_ctx (fp16)
    float inv0 = 1.f / l_i[0], inv1 = 1.f / l_i[1];
    int row_g = b * SEQ + q0 + r0;
    __half* orow0 = g_ctx + (size_t)row_g * EMB + h * HD;
    __half* orow1 = orow0 + (size_t)8 * EMB;
    #pragma unroll
    for (int na = 0; na < 8; na++) {
        int col = na * 8 + 2 * t;
        *(unsigned*)(orow0 + col) = packh2(o[na][0] * inv0, o[na][1] * inv0);
        *(unsigned*)(orow1 + col) = packh2(o[na][2] * inv1, o[na][3] * inv1);
    }
}

// ---------------------------------------------------------------------------
extern "C" void kernel_launch(void* const* d_in, const int* in_sizes, int n_in,
                              void* d_out, int out_size)
{
    (void)in_sizes; (void)n_in; (void)out_size;
    const float* qkv   = (const float*)d_in[0];
    const float* w_in  = (const float*)d_in[1];
    const float* b_in  = (const float*)d_in[2];
    const float* w_out = (const float*)d_in[3];
    const float* b_out = (const float*)d_in[4];
    float* out = (float*)d_out;

    int gemm_smem = 4 * 128 * TSH * sizeof(__half);   // 40960
    int attn_smem = 256 * QST * sizeof(__half);       // 36864
    cudaFuncSetAttribute(gemm_f16<0>, cudaFuncAttributeMaxDynamicSharedMemorySize, gemm_smem);
    cudaFuncSetAttribute(gemm_f16<1>, cudaFuncAttributeMaxDynamicSharedMemorySize, gemm_smem);
    cudaFuncSetAttribute(attn_f16, cudaFuncAttributeMaxDynamicSharedMemorySize, attn_smem);

    // Pre-pass: f32 -> fp16
    __half* d_qkv16, *d_win16, *d_wout16;
    cudaGetSymbolAddress((void**)&d_qkv16,  g_qkv16);
    cudaGetSymbolAddress((void**)&d_win16,  g_win16);
    cudaGetSymbolAddress((void**)&d_wout16, g_wout16);
    to_half<<<(TOK * EMB / 4 + 255) / 256, 256>>>((const float4*)qkv, (uint2*)d_qkv16, TOK * EMB / 4);
    to_half<<<(3 * EMB * EMB / 4 + 255) / 256, 256>>>((const float4*)w_in, (uint2*)d_win16, 3 * EMB * EMB / 4);
    to_half<<<(EMB * EMB / 4 + 255) / 256, 256>>>((const float4*)w_out, (uint2*)d_wout16, EMB * EMB / 4);

    dim3 g1(3 * EMB / 128, TOK / 128);
    gemm_f16<0><<<g1, 256, gemm_smem>>>(b_in, nullptr, 3 * EMB, EMB);

    dim3 g2(SEQ / 128, NH, BATCH);
    attn_f16<<<g2, 256, attn_smem>>>();

    dim3 g3(EMB / 128, TOK / 128);
    gemm_f16<1><<<g3, 256, gemm_smem>>>(b_out, out, EMB, EMB);
}

// round 12
// speedup vs baseline: 6.6368x; 1.0938x over previous
#include <cuda_runtime.h>
#include <cuda_fp16.h>
#include <math.h>
#include <stdint.h>

#define EMB   1024
#define SEQ   1024
#define BATCH 8
#define NH    16
#define HD    64
#define TOK   (BATCH*SEQ)   // 8192

// Scratch — fp16 everywhere
__device__ __half g_qkv16[(size_t)TOK * EMB];
__device__ __half g_win16[(size_t)3 * EMB * EMB];
__device__ __half g_wout16[(size_t)EMB * EMB];
__device__ __half g_proj[(size_t)TOK * 3 * EMB];
__device__ __half g_ctx[(size_t)TOK * EMB];

// ---------------------------------------------------------------------------
__device__ __forceinline__ float ex2(float x) {
    float y; asm("ex2.approx.ftz.f32 %0, %1;" : "=f"(y) : "f"(x)); return y;
}
__device__ __forceinline__ uint32_t s2u(const void* p) {
    return (uint32_t)__cvta_generic_to_shared(p);
}
__device__ __forceinline__ void mma_f16(float c[4], const unsigned a[4],
                                        unsigned b0, unsigned b1) {
    asm volatile(
        "mma.sync.aligned.m16n8k16.row.col.f32.f16.f16.f32 "
        "{%0,%1,%2,%3}, {%4,%5,%6,%7}, {%8,%9}, {%0,%1,%2,%3};"
        : "+f"(c[0]), "+f"(c[1]), "+f"(c[2]), "+f"(c[3])
        : "r"(a[0]), "r"(a[1]), "r"(a[2]), "r"(a[3]), "r"(b0), "r"(b1));
}
__device__ __forceinline__ void ldsm_x4(unsigned r[4], uint32_t addr) {
    asm volatile("ldmatrix.sync.aligned.m8n8.x4.shared.b16 {%0,%1,%2,%3}, [%4];"
        : "=r"(r[0]), "=r"(r[1]), "=r"(r[2]), "=r"(r[3]) : "r"(addr));
}
__device__ __forceinline__ void ldsm_x4_t(unsigned r[4], uint32_t addr) {
    asm volatile("ldmatrix.sync.aligned.m8n8.x4.trans.shared.b16 {%0,%1,%2,%3}, [%4];"
        : "=r"(r[0]), "=r"(r[1]), "=r"(r[2]), "=r"(r[3]) : "r"(addr));
}
__device__ __forceinline__ unsigned packh2(float a, float b) {
    __half2 h = __floats2half2_rn(a, b);
    return *(unsigned*)&h;
}

// ---------------------------------------------------------------------------
__global__ __launch_bounds__(256) void to_half(const float4* __restrict__ src,
                                               uint2* __restrict__ dst, int n4)
{
    int i = blockIdx.x * blockDim.x + threadIdx.x;
    if (i < n4) {
        float4 v = src[i];
        uint2 o = { packh2(v.x, v.y), packh2(v.z, v.w) };
        dst[i] = o;
    }
}

// ---------------------------------------------------------------------------
// GEMM: CTA 128x128, 4 warps (2x2), warp tile 64x64, BK=32, dbl-buffered.
// MODE 0: A=g_qkv16, B=g_win16, C=g_proj (fp16). MODE 1: A=g_ctx, B=g_wout16, C f32.
// ---------------------------------------------------------------------------
#define BK  32
#define TSH 40

template<int MODE>
__global__ __launch_bounds__(128, 2) void gemm_f16(
    const float* __restrict__ bias,
    float* __restrict__ Cext,
    int N, int K)
{
    extern __shared__ __half smh[];
    __half* Abuf0 = smh;
    __half* Abuf1 = smh + 128 * TSH;
    __half* Bbuf0 = smh + 2 * 128 * TSH;
    __half* Bbuf1 = smh + 3 * 128 * TSH;

    int tid  = threadIdx.x;
    int lane = tid & 31, w = tid >> 5;        // 4 warps
    int g = lane >> 2, t = lane & 3;
    int wm = (w >> 1) * 64, wn = (w & 1) * 64;
    int bm = blockIdx.y * 128, bn = blockIdx.x * 128;

    int lr = tid >> 2;        // 0..31
    int lc = (tid & 3) * 8;   // 0,8,16,24 (halves)

    const __half* Ah = (MODE == 0) ? g_qkv16 : g_ctx;
    const __half* Bh = (MODE == 0) ? g_win16 : g_wout16;
    const __half* Ap = Ah + (size_t)(bm + lr) * K + lc;
    const __half* Bp = Bh + (size_t)(bn + lr) * K + lc;

    int a_off = (wm + (lane & 15)) * TSH * 2 + (lane >> 4) * 16;
    int b_off = (wn + (lane & 7) + 8 * (lane >> 4)) * TSH * 2 + ((lane >> 3) & 1) * 16;

    uint4 rah[4], rbh[4];

    auto LDG = [&](int chunk) {
        #pragma unroll
        for (int i = 0; i < 4; i++) {
            rah[i] = *(const uint4*)(Ap + chunk * BK + (size_t)(32 * i) * K);
            rbh[i] = *(const uint4*)(Bp + chunk * BK + (size_t)(32 * i) * K);
        }
    };
    auto STS = [&](__half* as, __half* bs) {
        #pragma unroll
        for (int i = 0; i < 4; i++) {
            int r = lr + 32 * i;
            *(uint4*)(as + r * TSH + lc) = rah[i];
            *(uint4*)(bs + r * TSH + lc) = rbh[i];
        }
    };

    float acc[4][8][4];
    #pragma unroll
    for (int ma = 0; ma < 4; ma++)
        #pragma unroll
        for (int na = 0; na < 8; na++)
            #pragma unroll
            for (int j = 0; j < 4; j++) acc[ma][na][j] = 0.f;

    auto COMPUTE = [&](const __half* as, const __half* bs) {
        uint32_t abase = s2u(as) + a_off;
        uint32_t bbase = s2u(bs) + b_off;
        #pragma unroll
        for (int s = 0; s < 2; s++) {
            uint32_t ko = s * 32;
            unsigned af[4][4];
            #pragma unroll
            for (int ma = 0; ma < 4; ma++)
                ldsm_x4(af[ma], abase + ma * 16 * TSH * 2 + ko);
            #pragma unroll
            for (int j = 0; j < 4; j++) {
                unsigned bf[4];
                ldsm_x4(bf, bbase + j * 16 * TSH * 2 + ko);
                #pragma unroll
                for (int ma = 0; ma < 4; ma++) {
                    mma_f16(acc[ma][2 * j],     af[ma], bf[0], bf[1]);
                    mma_f16(acc[ma][2 * j + 1], af[ma], bf[2], bf[3]);
                }
            }
        }
    };

    int nch = K / BK;
    LDG(0);
    STS(Abuf0, Bbuf0);
    LDG(1);
    __syncthreads();

    for (int i = 0; i < nch; i++) {
        int cur = i & 1;
        if (i + 1 < nch) {
            if (cur) STS(Abuf0, Bbuf0); else STS(Abuf1, Bbuf1);
        }
        if (i + 2 < nch) LDG(i + 2);
        if (cur) COMPUTE(Abuf1, Bbuf1); else COMPUTE(Abuf0, Bbuf0);
        __syncthreads();
    }

    #pragma unroll
    for (int ma = 0; ma < 4; ma++) {
        int r0 = bm + wm + ma * 16 + g;
        #pragma unroll
        for (int na = 0; na < 8; na++) {
            int col = bn + wn + na * 8 + 2 * t;
            float2 bv = *(const float2*)(bias + col);
            if (MODE == 0) {
                *(unsigned*)(g_proj + (size_t)r0 * N + col) =
                    packh2(acc[ma][na][0] + bv.x, acc[ma][na][1] + bv.y);
                *(unsigned*)(g_proj + (size_t)(r0 + 8) * N + col) =
                    packh2(acc[ma][na][2] + bv.x, acc[ma][na][3] + bv.y);
            } else {
                float2 o0 = { acc[ma][na][0] + bv.x, acc[ma][na][1] + bv.y };
                *(float2*)(Cext + (size_t)r0 * N + col) = o0;
                float2 o1 = { acc[ma][na][2] + bv.x, acc[ma][na][3] + bv.y };
                *(float2*)(Cext + (size_t)(r0 + 8) * N + col) = o1;
            }
        }
    }
}

// ---------------------------------------------------------------------------
// Flash attention: 4 warps, warp tile m32 (32 q-rows/warp), 128 q/CTA.
// K/V read once per warp per kv-block for 2x the flops of R11.
// ---------------------------------------------------------------------------
#define QST 72

__global__ __launch_bounds__(128, 2) void attn_f16()
{
    extern __shared__ __half sma[];
    __half* Qs = sma;                // [128][QST]
    __half* Ks = sma + 128 * QST;    // [64][QST]
    __half* Vs = sma + 192 * QST;    // [64][QST]

    int tid = threadIdx.x, lane = tid & 31, w = tid >> 5;  // 4 warps
    int g = lane >> 2, t = lane & 3;
    int h = blockIdx.y, b = blockIdx.z, q0 = blockIdx.x * 128;

    const __half* base = g_proj + (size_t)b * SEQ * (3 * EMB) + h * HD;
    const float SCL = 0.125f * 1.4426950408889634f;
    const __half2 SCL2 = __float2half2_rn(SCL);

    int aoff = (w * 32 + (lane & 15)) * QST * 2 + (lane >> 4) * 16;
    int boff = ((lane & 7) + 8 * (lane >> 4)) * QST * 2 + ((lane >> 3) & 1) * 16;
    int voff = ((lane & 7) + 8 * ((lane >> 3) & 1)) * QST + 8 * (lane >> 4);
    uint32_t qbase = s2u(Qs) + aoff;
    uint32_t kbase = s2u(Ks) + boff;
    uint32_t vbase = s2u(Vs) + voff * 2;

    // Stage Q (one 64-half row per thread, scale by SCL)
    {
        const uint4* src = (const uint4*)(base + (size_t)(q0 + tid) * (3 * EMB));
        uint4* dst = (uint4*)(Qs + tid * QST);
        #pragma unroll
        for (int i = 0; i < 8; i++) {
            uint4 v = src[i];
            __half2* hv = (__half2*)&v;
            #pragma unroll
            for (int j = 0; j < 4; j++) hv[j] = __hmul2(hv[j], SCL2);
            dst[i] = v;
        }
    }
    __syncthreads();

    // Hoist Q fragments: qf[k16 step][m16 half]
    unsigned qf[4][2][4];
    #pragma unroll
    for (int ks = 0; ks < 4; ks++)
        #pragma unroll
        for (int ma = 0; ma < 2; ma++)
            ldsm_x4(qf[ks][ma], qbase + ma * 16 * QST * 2 + ks * 32);

    float m_i[2][2], l_i[2][2];
    #pragma unroll
    for (int ma = 0; ma < 2; ma++)
        #pragma unroll
        for (int hf = 0; hf < 2; hf++) { m_i[ma][hf] = -1e30f; l_i[ma][hf] = 0.f; }
    float o[2][8][4];
    #pragma unroll
    for (int ma = 0; ma < 2; ma++)
        #pragma unroll
        for (int na = 0; na < 8; na++)
            #pragma unroll
            for (int j = 0; j < 4; j++) o[ma][na][j] = 0.f;

    for (int kb = 0; kb < 16; kb++) {
        __syncthreads();
        // Stage K and V (2 threads per 64-half row)
        {
            int r = tid >> 1, cb = (tid & 1) * 32;
            const uint4* ks4 = (const uint4*)(base + EMB     + (size_t)(kb * 64 + r) * (3 * EMB) + cb);
            const uint4* vs4 = (const uint4*)(base + 2 * EMB + (size_t)(kb * 64 + r) * (3 * EMB) + cb);
            uint4* kd = (uint4*)(Ks + r * QST + cb);
            uint4* vd = (uint4*)(Vs + r * QST + cb);
            #pragma unroll
            for (int i = 0; i < 4; i++) { kd[i] = ks4[i]; vd[i] = vs4[i]; }
        }
        __syncthreads();

        // S = Q K^T (warp m32 x n64)
        float sc[2][8][4];
        #pragma unroll
        for (int ma = 0; ma < 2; ma++)
            #pragma unroll
            for (int na = 0; na < 8; na++)
                #pragma unroll
                for (int j = 0; j < 4; j++) sc[ma][na][j] = 0.f;

        #pragma unroll
        for (int ks = 0; ks < 4; ks++) {
            uint32_t ko = ks * 32;
            #pragma unroll
            for (int j = 0; j < 4; j++) {
                unsigned bf[4];
                ldsm_x4(bf, kbase + j * 16 * QST * 2 + ko);
                #pragma unroll
                for (int ma = 0; ma < 2; ma++) {
                    mma_f16(sc[ma][2 * j],     qf[ks][ma], bf[0], bf[1]);
                    mma_f16(sc[ma][2 * j + 1], qf[ks][ma], bf[2], bf[3]);
                }
            }
        }

        // Online softmax (exp2 domain); P into registers
        unsigned ph[2][2][8];   // [ma][half][na]
        #pragma unroll
        for (int ma = 0; ma < 2; ma++) {
            #pragma unroll
            for (int hf = 0; hf < 2; hf++) {
                float rm = -1e30f;
                #pragma unroll
                for (int na = 0; na < 8; na++)
                    rm = fmaxf(rm, fmaxf(sc[ma][na][hf*2], sc[ma][na][hf*2+1]));
                rm = fmaxf(rm, __shfl_xor_sync(0xffffffffu, rm, 1));
                rm = fmaxf(rm, __shfl_xor_sync(0xffffffffu, rm, 2));
                float mn = fmaxf(m_i[ma][hf], rm);
                float al = ex2(m_i[ma][hf] - mn);
                float rs = 0.f;
                #pragma unroll
                for (int na = 0; na < 8; na++) {
                    float p0 = ex2(sc[ma][na][hf*2]   - mn);
                    float p1 = ex2(sc[ma][na][hf*2+1] - mn);
                    rs += p0 + p1;
                    ph[ma][hf][na] = packh2(p0, p1);
                    o[ma][na][hf*2]   *= al;
                    o[ma][na][hf*2+1] *= al;
                }
                rs += __shfl_xor_sync(0xffffffffu, rs, 1);
                rs += __shfl_xor_sync(0xffffffffu, rs, 2);
                l_i[ma][hf] = l_i[ma][hf] * al + rs;
                m_i[ma][hf] = mn;
            }
        }

        // O += P V  (V frags shared across ma)
        #pragma unroll
        for (int ks = 0; ks < 4; ks++) {
            unsigned af0[4] = { ph[0][0][2*ks], ph[0][1][2*ks],
                                ph[0][0][2*ks+1], ph[0][1][2*ks+1] };
            unsigned af1[4] = { ph[1][0][2*ks], ph[1][1][2*ks],
                                ph[1][0][2*ks+1], ph[1][1][2*ks+1] };
            #pragma unroll
            for (int j = 0; j < 4; j++) {
                unsigned bf[4];
                ldsm_x4_t(bf, vbase + (ks * 16 * QST + j * 16) * 2);
                mma_f16(o[0][2 * j],     af0, bf[0], bf[1]);
                mma_f16(o[0][2 * j + 1], af0, bf[2], bf[3]);
                mma_f16(o[1][2 * j],     af1, bf[0], bf[1]);
                mma_f16(o[1][2 * j + 1], af1, bf[2], bf[3]);
            }
        }
    }

    // Epilogue -> g_ctx (fp16)
    #pragma unroll
    for (int ma = 0; ma < 2; ma++) {
        float inv0 = 1.f / l_i[ma][0], inv1 = 1.f / l_i[ma][1];
        int row_g = b * SEQ + q0 + w * 32 + ma * 16 + g;
        __half* orow0 = g_ctx + (size_t)row_g * EMB + h * HD;
        __half* orow1 = orow0 + (size_t)8 * EMB;
        #pragma unroll
        for (int na = 0; na < 8; na++) {
            int col = na * 8 + 2 * t;
            *(unsigned*)(orow0 + col) = packh2(o[ma][na][0] * inv0, o[ma][na][1] * inv0);
            *(unsigned*)(orow1 + col) = packh2(o[ma][na][2] * inv1, o[ma][na][3] * inv1);
        }
    }
}

// ---------------------------------------------------------------------------
extern "C" void kernel_launch(void* const* d_in, const int* in_sizes, int n_in,
                              void* d_out, int out_size)
{
    (void)in_sizes; (void)n_in; (void)out_size;
    const float* qkv   = (const float*)d_in[0];
    const float* w_in  = (const float*)d_in[1];
    const float* b_in  = (const float*)d_in[2];
    const float* w_out = (const float*)d_in[3];
    const float* b_out = (const float*)d_in[4];
    float* out = (float*)d_out;

    int gemm_smem = 4 * 128 * TSH * sizeof(__half);   // 40960
    int attn_smem = 256 * QST * sizeof(__half);       // 36864
    cudaFuncSetAttribute(gemm_f16<0>, cudaFuncAttributeMaxDynamicSharedMemorySize, gemm_smem);
    cudaFuncSetAttribute(gemm_f16<1>, cudaFuncAttributeMaxDynamicSharedMemorySize, gemm_smem);
    cudaFuncSetAttribute(attn_f16, cudaFuncAttributeMaxDynamicSharedMemorySize, attn_smem);

    __half* d_qkv16, *d_win16, *d_wout16;
    cudaGetSymbolAddress((void**)&d_qkv16,  g_qkv16);
    cudaGetSymbolAddress((void**)&d_win16,  g_win16);
    cudaGetSymbolAddress((void**)&d_wout16, g_wout16);
    to_half<<<(TOK * EMB / 4 + 255) / 256, 256>>>((const float4*)qkv, (uint2*)d_qkv16, TOK * EMB / 4);
    to_half<<<(3 * EMB * EMB / 4 + 255) / 256, 256>>>((const float4*)w_in, (uint2*)d_win16, 3 * EMB * EMB / 4);
    to_half<<<(EMB * EMB / 4 + 255) / 256, 256>>>((const float4*)w_out, (uint2*)d_wout16, EMB * EMB / 4);

    dim3 g1(3 * EMB / 128, TOK / 128);
    gemm_f16<0><<<g1, 128, gemm_smem>>>(b_in, nullptr, 3 * EMB, EMB);

    dim3 g2(SEQ / 128, NH, BATCH);
    attn_f16<<<g2, 128, attn_smem>>>();

    dim3 g3(EMB / 128, TOK / 128);
    gemm_f16<1><<<g3, 128, gemm_smem>>>(b_out, out, EMB, EMB);
}

// round 13
// speedup vs baseline: 7.0873x; 1.0679x over previous
#include <cuda_runtime.h>
#include <cuda_fp16.h>
#include <math.h>
#include <stdint.h>

#define EMB   1024
#define SEQ   1024
#define BATCH 8
#define NH    16
#define HD    64
#define TOK   (BATCH*SEQ)   // 8192

// Scratch — fp16 everywhere
__device__ __half g_qkv16[(size_t)TOK * EMB];
__device__ __half g_win16[(size_t)3 * EMB * EMB];
__device__ __half g_wout16[(size_t)EMB * EMB];
__device__ __half g_proj[(size_t)TOK * 3 * EMB];
__device__ __half g_ctx[(size_t)TOK * EMB];

// ---------------------------------------------------------------------------
__device__ __forceinline__ float ex2(float x) {
    float y; asm("ex2.approx.ftz.f32 %0, %1;" : "=f"(y) : "f"(x)); return y;
}
__device__ __forceinline__ uint32_t s2u(const void* p) {
    return (uint32_t)__cvta_generic_to_shared(p);
}
__device__ __forceinline__ void mma_f16(float c[4], const unsigned a[4],
                                        unsigned b0, unsigned b1) {
    asm volatile(
        "mma.sync.aligned.m16n8k16.row.col.f32.f16.f16.f32 "
        "{%0,%1,%2,%3}, {%4,%5,%6,%7}, {%8,%9}, {%0,%1,%2,%3};"
        : "+f"(c[0]), "+f"(c[1]), "+f"(c[2]), "+f"(c[3])
        : "r"(a[0]), "r"(a[1]), "r"(a[2]), "r"(a[3]), "r"(b0), "r"(b1));
}
__device__ __forceinline__ void ldsm_x4(unsigned r[4], uint32_t addr) {
    asm volatile("ldmatrix.sync.aligned.m8n8.x4.shared.b16 {%0,%1,%2,%3}, [%4];"
        : "=r"(r[0]), "=r"(r[1]), "=r"(r[2]), "=r"(r[3]) : "r"(addr));
}
__device__ __forceinline__ void ldsm_x4_t(unsigned r[4], uint32_t addr) {
    asm volatile("ldmatrix.sync.aligned.m8n8.x4.trans.shared.b16 {%0,%1,%2,%3}, [%4];"
        : "=r"(r[0]), "=r"(r[1]), "=r"(r[2]), "=r"(r[3]) : "r"(addr));
}
__device__ __forceinline__ unsigned packh2(float a, float b) {
    __half2 h = __floats2half2_rn(a, b);
    return *(unsigned*)&h;
}
__device__ __forceinline__ void cp16(uint32_t dst, const void* src) {
    asm volatile("cp.async.cg.shared.global [%0], [%1], 16;" :: "r"(dst), "l"(src));
}
#define CP_COMMIT() asm volatile("cp.async.commit_group;")
#define CP_WAIT(n)  asm volatile("cp.async.wait_group %0;" :: "n"(n))

// ---------------------------------------------------------------------------
__global__ __launch_bounds__(256) void to_half(const float4* __restrict__ src,
                                               uint2* __restrict__ dst, int n4)
{
    int i = blockIdx.x * blockDim.x + threadIdx.x;
    if (i < n4) {
        float4 v = src[i];
        uint2 o = { packh2(v.x, v.y), packh2(v.z, v.w) };
        dst[i] = o;
    }
}

// ---------------------------------------------------------------------------
// GEMM: CTA 128x128, 4 warps (2x2), warp tile 64x64, BK=32.
// 3-stage cp.async pipeline. MODE 0: g_qkv16 x g_win16 -> g_proj (fp16).
// MODE 1: g_ctx x g_wout16 -> Cext (f32).
// ---------------------------------------------------------------------------
#define BK  32
#define TSH 40

template<int MODE>
__global__ __launch_bounds__(128, 2) void gemm_f16(
    const float* __restrict__ bias,
    float* __restrict__ Cext,
    int N, int K)
{
    extern __shared__ __half smh[];   // 3 stages x (A 128*TSH | B 128*TSH)

    int tid  = threadIdx.x;
    int lane = tid & 31, w = tid >> 5;
    int g = lane >> 2, t = lane & 3;
    int wm = (w >> 1) * 64, wn = (w & 1) * 64;
    int bm = blockIdx.y * 128, bn = blockIdx.x * 128;

    int lr = tid >> 2;        // 0..31
    int lc = (tid & 3) * 8;   // 0,8,16,24 halves (16B)

    const __half* Ah = (MODE == 0) ? g_qkv16 : g_ctx;
    const __half* Bh = (MODE == 0) ? g_win16 : g_wout16;
    const __half* Ap = Ah + (size_t)(bm + lr) * K + lc;
    const __half* Bp = Bh + (size_t)(bn + lr) * K + lc;

    int a_off = (wm + (lane & 15)) * TSH * 2 + (lane >> 4) * 16;
    int b_off = (wn + (lane & 7) + 8 * (lane >> 4)) * TSH * 2 + ((lane >> 3) & 1) * 16;

    auto ISSUE = [&](int chunk) {
        __half* as = smh + (chunk % 3) * 2 * 128 * TSH;
        __half* bs = as + 128 * TSH;
        const __half* ap = Ap + chunk * BK;
        const __half* bp = Bp + chunk * BK;
        #pragma unroll
        for (int i = 0; i < 4; i++) {
            int r = lr + 32 * i;
            cp16(s2u(as + r * TSH + lc), ap + (size_t)(32 * i) * K);
            cp16(s2u(bs + r * TSH + lc), bp + (size_t)(32 * i) * K);
        }
        CP_COMMIT();
    };

    float acc[4][8][4];
    #pragma unroll
    for (int ma = 0; ma < 4; ma++)
        #pragma unroll
        for (int na = 0; na < 8; na++)
            #pragma unroll
            for (int j = 0; j < 4; j++) acc[ma][na][j] = 0.f;

    auto COMPUTE = [&](const __half* as, const __half* bs) {
        uint32_t abase = s2u(as) + a_off;
        uint32_t bbase = s2u(bs) + b_off;
        #pragma unroll
        for (int s = 0; s < 2; s++) {
            uint32_t ko = s * 32;
            unsigned af[4][4];
            #pragma unroll
            for (int ma = 0; ma < 4; ma++)
                ldsm_x4(af[ma], abase + ma * 16 * TSH * 2 + ko);
            #pragma unroll
            for (int j = 0; j < 4; j++) {
                unsigned bf[4];
                ldsm_x4(bf, bbase + j * 16 * TSH * 2 + ko);
                #pragma unroll
                for (int ma = 0; ma < 4; ma++) {
                    mma_f16(acc[ma][2 * j],     af[ma], bf[0], bf[1]);
                    mma_f16(acc[ma][2 * j + 1], af[ma], bf[2], bf[3]);
                }
            }
        }
    };

    int nch = K / BK;
    ISSUE(0);
    ISSUE(1);

    for (int i = 0; i < nch; i++) {
        if (i + 1 < nch) { CP_WAIT(1); } else { CP_WAIT(0); }
        __syncthreads();                 // chunk i visible; compute(i-1) done everywhere
        if (i + 2 < nch) ISSUE(i + 2);   // into stage (i+2)%3 = (i-1)%3, safe after sync
        __half* as = smh + (i % 3) * 2 * 128 * TSH;
        COMPUTE(as, as + 128 * TSH);
    }

    #pragma unroll
    for (int ma = 0; ma < 4; ma++) {
        int r0 = bm + wm + ma * 16 + g;
        #pragma unroll
        for (int na = 0; na < 8; na++) {
            int col = bn + wn + na * 8 + 2 * t;
            float2 bv = *(const float2*)(bias + col);
            if (MODE == 0) {
                *(unsigned*)(g_proj + (size_t)r0 * N + col) =
                    packh2(acc[ma][na][0] + bv.x, acc[ma][na][1] + bv.y);
                *(unsigned*)(g_proj + (size_t)(r0 + 8) * N + col) =
                    packh2(acc[ma][na][2] + bv.x, acc[ma][na][3] + bv.y);
            } else {
                float2 o0 = { acc[ma][na][0] + bv.x, acc[ma][na][1] + bv.y };
                *(float2*)(Cext + (size_t)r0 * N + col) = o0;
                float2 o1 = { acc[ma][na][2] + bv.x, acc[ma][na][3] + bv.y };
                *(float2*)(Cext + (size_t)(r0 + 8) * N + col) = o1;
            }
        }
    }
}

// ---------------------------------------------------------------------------
// Flash attention: 4 warps, m32 warp tile, 128 q/CTA. K/V double-buffered
// via cp.async — kb+1 loads overlap kb compute.
// ---------------------------------------------------------------------------
#define QST 72

__global__ __launch_bounds__(128, 2) void attn_f16()
{
    extern __shared__ __half sma[];
    __half* Qs = sma;                          // [128][QST]
    __half* Kb[2] = { sma + 128 * QST, sma + 192 * QST };
    __half* Vb[2] = { sma + 256 * QST, sma + 320 * QST };

    int tid = threadIdx.x, lane = tid & 31, w = tid >> 5;
    int g = lane >> 2, t = lane & 3;
    int h = blockIdx.y, b = blockIdx.z, q0 = blockIdx.x * 128;

    const __half* base = g_proj + (size_t)b * SEQ * (3 * EMB) + h * HD;
    const float SCL = 0.125f * 1.4426950408889634f;
    const __half2 SCL2 = __float2half2_rn(SCL);

    int aoff = (w * 32 + (lane & 15)) * QST * 2 + (lane >> 4) * 16;
    int boff = ((lane & 7) + 8 * (lane >> 4)) * QST * 2 + ((lane >> 3) & 1) * 16;
    int voff = (((lane & 7) + 8 * ((lane >> 3) & 1)) * QST + 8 * (lane >> 4)) * 2;
    uint32_t qbase = s2u(Qs) + aoff;
    uint32_t kbase[2] = { s2u(Kb[0]) + boff, s2u(Kb[1]) + boff };
    uint32_t vbase[2] = { s2u(Vb[0]) + voff, s2u(Vb[1]) + voff };

    auto ISSUE_KV = [&](int kb) {
        int bi = kb & 1;
        int r = tid >> 1, cb = (tid & 1) * 32;
        const __half* ksrc = base + EMB + (size_t)(kb * 64 + r) * (3 * EMB) + cb;
        const __half* vsrc = ksrc + EMB;
        __half* kd = Kb[bi] + r * QST + cb;
        __half* vd = Vb[bi] + r * QST + cb;
        #pragma unroll
        for (int i = 0; i < 4; i++) {
            cp16(s2u(kd + i * 8), ksrc + i * 8);
            cp16(s2u(vd + i * 8), vsrc + i * 8);
        }
        CP_COMMIT();
    };

    ISSUE_KV(0);   // in flight during Q staging

    // Stage Q (one 64-half row per thread, scale by SCL)
    {
        const uint4* src = (const uint4*)(base + (size_t)(q0 + tid) * (3 * EMB));
        uint4* dst = (uint4*)(Qs + tid * QST);
        #pragma unroll
        for (int i = 0; i < 8; i++) {
            uint4 v = src[i];
            __half2* hv = (__half2*)&v;
            #pragma unroll
            for (int j = 0; j < 4; j++) hv[j] = __hmul2(hv[j], SCL2);
            dst[i] = v;
        }
    }
    __syncthreads();

    // Hoist Q fragments: qf[k16 step][m16 half]
    unsigned qf[4][2][4];
    #pragma unroll
    for (int ks = 0; ks < 4; ks++)
        #pragma unroll
        for (int ma = 0; ma < 2; ma++)
            ldsm_x4(qf[ks][ma], qbase + ma * 16 * QST * 2 + ks * 32);

    float m_i[2][2], l_i[2][2];
    #pragma unroll
    for (int ma = 0; ma < 2; ma++)
        #pragma unroll
        for (int hf = 0; hf < 2; hf++) { m_i[ma][hf] = -1e30f; l_i[ma][hf] = 0.f; }
    float o[2][8][4];
    #pragma unroll
    for (int ma = 0; ma < 2; ma++)
        #pragma unroll
        for (int na = 0; na < 8; na++)
            #pragma unroll
            for (int j = 0; j < 4; j++) o[ma][na][j] = 0.f;

    for (int kb = 0; kb < 16; kb++) {
        int bi = kb & 1;
        CP_WAIT(0);          // only kb's group outstanding here
        __syncthreads();     // kb data visible; compute(kb-1) done everywhere
        if (kb + 1 < 16) ISSUE_KV(kb + 1);   // overlaps compute below

        // S = Q K^T (warp m32 x n64)
        float sc[2][8][4];
        #pragma unroll
        for (int ma = 0; ma < 2; ma++)
            #pragma unroll
            for (int na = 0; na < 8; na++)
                #pragma unroll
                for (int j = 0; j < 4; j++) sc[ma][na][j] = 0.f;

        #pragma unroll
        for (int ks = 0; ks < 4; ks++) {
            uint32_t ko = ks * 32;
            #pragma unroll
            for (int j = 0; j < 4; j++) {
                unsigned bf[4];
                ldsm_x4(bf, kbase[bi] + j * 16 * QST * 2 + ko);
                #pragma unroll
                for (int ma = 0; ma < 2; ma++) {
                    mma_f16(sc[ma][2 * j],     qf[ks][ma], bf[0], bf[1]);
                    mma_f16(sc[ma][2 * j + 1], qf[ks][ma], bf[2], bf[3]);
                }
            }
        }

        // Online softmax (exp2 domain); P into registers
        unsigned ph[2][2][8];
        #pragma unroll
        for (int ma = 0; ma < 2; ma++) {
            #pragma unroll
            for (int hf = 0; hf < 2; hf++) {
                float rm = -1e30f;
                #pragma unroll
                for (int na = 0; na < 8; na++)
                    rm = fmaxf(rm, fmaxf(sc[ma][na][hf*2], sc[ma][na][hf*2+1]));
                rm = fmaxf(rm, __shfl_xor_sync(0xffffffffu, rm, 1));
                rm = fmaxf(rm, __shfl_xor_sync(0xffffffffu, rm, 2));
                float mn = fmaxf(m_i[ma][hf], rm);
                float al = ex2(m_i[ma][hf] - mn);
                float rs = 0.f;
                #pragma unroll
                for (int na = 0; na < 8; na++) {
                    float p0 = ex2(sc[ma][na][hf*2]   - mn);
                    float p1 = ex2(sc[ma][na][hf*2+1] - mn);
                    rs += p0 + p1;
                    ph[ma][hf][na] = packh2(p0, p1);
                    o[ma][na][hf*2]   *= al;
                    o[ma][na][hf*2+1] *= al;
                }
                rs += __shfl_xor_sync(0xffffffffu, rs, 1);
                rs += __shfl_xor_sync(0xffffffffu, rs, 2);
                l_i[ma][hf] = l_i[ma][hf] * al + rs;
                m_i[ma][hf] = mn;
            }
        }

        // O += P V  (V frags shared across ma)
        #pragma unroll
        for (int ks = 0; ks < 4; ks++) {
            unsigned af0[4] = { ph[0][0][2*ks], ph[0][1][2*ks],
                                ph[0][0][2*ks+1], ph[0][1][2*ks+1] };
            unsigned af1[4] = { ph[1][0][2*ks], ph[1][1][2*ks],
                                ph[1][0][2*ks+1], ph[1][1][2*ks+1] };
            #pragma unroll
            for (int j = 0; j < 4; j++) {
                unsigned bf[4];
                ldsm_x4_t(bf, vbase[bi] + (ks * 16 * QST + j * 16) * 2);
                mma_f16(o[0][2 * j],     af0, bf[0], bf[1]);
                mma_f16(o[0][2 * j + 1], af0, bf[2], bf[3]);
                mma_f16(o[1][2 * j],     af1, bf[0], bf[1]);
                mma_f16(o[1][2 * j + 1], af1, bf[2], bf[3]);
            }
        }
    }

    // Epilogue -> g_ctx (fp16)
    #pragma unroll
    for (int ma = 0; ma < 2; ma++) {
        float inv0 = 1.f / l_i[ma][0], inv1 = 1.f / l_i[ma][1];
        int row_g = b * SEQ + q0 + w * 32 + ma * 16 + g;
        __half* orow0 = g_ctx + (size_t)row_g * EMB + h * HD;
        __half* orow1 = orow0 + (size_t)8 * EMB;
        #pragma unroll
        for (int na = 0; na < 8; na++) {
            int col = na * 8 + 2 * t;
            *(unsigned*)(orow0 + col) = packh2(o[ma][na][0] * inv0, o[ma][na][1] * inv0);
            *(unsigned*)(orow1 + col) = packh2(o[ma][na][2] * inv1, o[ma][na][3] * inv1);
        }
    }
}

// ---------------------------------------------------------------------------
extern "C" void kernel_launch(void* const* d_in, const int* in_sizes, int n_in,
                              void* d_out, int out_size)
{
    (void)in_sizes; (void)n_in; (void)out_size;
    const float* qkv   = (const float*)d_in[0];
    const float* w_in  = (const float*)d_in[1];
    const float* b_in  = (const float*)d_in[2];
    const float* w_out = (const float*)d_in[3];
    const float* b_out = (const float*)d_in[4];
    float* out = (float*)d_out;

    int gemm_smem = 3 * 2 * 128 * TSH * sizeof(__half);   // 61440
    int attn_smem = 384 * QST * sizeof(__half);           // 55296
    cudaFuncSetAttribute(gemm_f16<0>, cudaFuncAttributeMaxDynamicSharedMemorySize, gemm_smem);
    cudaFuncSetAttribute(gemm_f16<1>, cudaFuncAttributeMaxDynamicSharedMemorySize, gemm_smem);
    cudaFuncSetAttribute(attn_f16, cudaFuncAttributeMaxDynamicSharedMemorySize, attn_smem);

    __half* d_qkv16, *d_win16, *d_wout16;
    cudaGetSymbolAddress((void**)&d_qkv16,  g_qkv16);
    cudaGetSymbolAddress((void**)&d_win16,  g_win16);
    cudaGetSymbolAddress((void**)&d_wout16, g_wout16);
    to_half<<<(TOK * EMB / 4 + 255) / 256, 256>>>((const float4*)qkv, (uint2*)d_qkv16, TOK * EMB / 4);
    to_half<<<(3 * EMB * EMB / 4 + 255) / 256, 256>>>((const float4*)w_in, (uint2*)d_win16, 3 * EMB * EMB / 4);
    to_half<<<(EMB * EMB / 4 + 255) / 256, 256>>>((const float4*)w_out, (uint2*)d_wout16, EMB * EMB / 4);

    dim3 g1(3 * EMB / 128, TOK / 128);
    gemm_f16<0><<<g1, 128, gemm_smem>>>(b_in, nullptr, 3 * EMB, EMB);

    dim3 g2(SEQ / 128, NH, BATCH);
    attn_f16<<<g2, 128, attn_smem>>>();

    dim3 g3(EMB / 128, TOK / 128);
    gemm_f16<1><<<g3, 128, gemm_smem>>>(b_out, out, EMB, EMB);
}